// round 1
// baseline (speedup 1.0000x reference)
#include <cuda_runtime.h>
#include <cstdint>
#include <cstddef>

// Shapes (compile-time constants)
#define BB   16
#define NN   1024
#define FIN  7
#define HH   8
#define DD   32
#define EMB  256   // HH*DD

// ---------------- scratch (static device memory; no allocations) ----------------
__device__ float g_Wh1[BB * HH * NN * DD];   // [b][h][n][d]  16 MB
__device__ float g_c1 [BB * HH * NN];        // [b][h][n]
__device__ float g_h1 [BB * NN * EMB];       // [b][n][h*32+d] 16 MB
__device__ float g_c2 [BB * HH * NN];
__device__ float g_zi [BB * HH * NN];        // 1/Z per row (layer 2)
__device__ float g_g  [BB * HH * NN];        // column sums of a2
__device__ float g_v  [HH * EMB];            // Wm[h] @ qsum[h]
__device__ float g_cb [HH];                  // bias term of s2
__device__ float g_p  [BB * EMB];            // pooled features

// ---------------- K1: Wh1 = x@Ws + bs, c1 ----------------
__global__ __launch_bounds__(256) void k1_wh1(
    const float* __restrict__ x,  const float* __restrict__ Ws,
    const float* __restrict__ bs, const float* __restrict__ qs,
    const float* __restrict__ qbs)
{
    int idx = blockIdx.x * blockDim.x + threadIdx.x;   // (b*8+h)*1024 + n
    int n = idx & (NN - 1);
    int h = (idx >> 10) & (HH - 1);
    int b = idx >> 13;

    float xv[FIN];
    const float* xr = x + ((size_t)(b * NN + n)) * FIN;
#pragma unroll
    for (int i = 0; i < FIN; i++) xv[i] = xr[i];

    const float* W = Ws + h * FIN * DD;
    float s = qbs[h];
    float* out = g_Wh1 + ((size_t)idx) * DD;
#pragma unroll
    for (int d = 0; d < DD; d++) {
        float acc = bs[h * DD + d];
#pragma unroll
        for (int i = 0; i < FIN; i++) acc += xv[i] * W[i * DD + d];
        out[d] = acc;
        s += acc * (qs[h * 2 * DD + d] + qs[h * 2 * DD + DD + d]);
    }
    g_c1[idx] = s > 0.f ? s : 0.01f * s;
}

// ---------------- K2: layer-1 attention (fused softmax * Wh) ----------------
// CTA: (h, i-block of 128, b). 128 threads, thread t owns row i=i0+t, 32 accs.
__global__ __launch_bounds__(128) void k2_attn1(const float* __restrict__ adj)
{
    __shared__ float adj_s[128][33];
    __shared__ float wh_s[32 * 32];

    int h = blockIdx.x, ib = blockIdx.y, b = blockIdx.z;
    int t = threadIdx.x;
    int i = ib * 128 + t;

    float c = g_c1[(b * HH + h) * NN + i];
    const float* whbase = g_Wh1 + ((size_t)(b * HH + h)) * NN * DD;
    const float* adjb   = adj + (size_t)b * NN * NN;

    float acc[DD];
#pragma unroll
    for (int d = 0; d < DD; d++) acc[d] = 0.f;
    float Z = 0.f;

#pragma unroll 1
    for (int j0 = 0; j0 < NN; j0 += 32) {
        __syncthreads();
        // adj tile 128x32 -> smem (coalesced float4 loads)
        {
            int r  = t >> 3;
            int c4 = (t & 7) * 4;
#pragma unroll
            for (int p = 0; p < 8; p++) {
                int row = p * 16 + r;
                float4 v = *reinterpret_cast<const float4*>(
                    adjb + (size_t)(ib * 128 + row) * NN + j0 + c4);
                adj_s[row][c4 + 0] = v.x; adj_s[row][c4 + 1] = v.y;
                adj_s[row][c4 + 2] = v.z; adj_s[row][c4 + 3] = v.w;
            }
        }
        // Wh tile 32x32 -> smem
        {
            const float4* src = reinterpret_cast<const float4*>(whbase + (size_t)j0 * DD);
            float4* dst = reinterpret_cast<float4*>(wh_s);
            dst[t]       = src[t];
            dst[t + 128] = src[t + 128];
        }
        __syncthreads();

#pragma unroll 4
        for (int jj = 0; jj < 32; jj++) {
            float e = __expf(c * adj_s[t][jj]);
            Z += e;
            const float4* w = reinterpret_cast<const float4*>(&wh_s[jj * 32]);
#pragma unroll
            for (int d4 = 0; d4 < 8; d4++) {
                float4 wv = w[d4];
                acc[d4 * 4 + 0] += e * wv.x;
                acc[d4 * 4 + 1] += e * wv.y;
                acc[d4 * 4 + 2] += e * wv.z;
                acc[d4 * 4 + 3] += e * wv.w;
            }
        }
    }
    float zi = 1.f / Z;
    float* out = g_h1 + ((size_t)(b * NN + i)) * EMB + h * DD;
#pragma unroll
    for (int d4 = 0; d4 < 8; d4++) {
        float4 v = make_float4(acc[d4 * 4 + 0] * zi, acc[d4 * 4 + 1] * zi,
                               acc[d4 * 4 + 2] * zi, acc[d4 * 4 + 3] * zi);
        reinterpret_cast<float4*>(out)[d4] = v;
    }
}

// ---------------- K3v: v[h][k] = sum_d Wm[h][k][d]*qsum[h][d]; cb[h] ----------------
__global__ __launch_bounds__(256) void k3v(
    const float* __restrict__ Wm, const float* __restrict__ bm,
    const float* __restrict__ qm, const float* __restrict__ qbm)
{
    int t = threadIdx.x;
#pragma unroll
    for (int p = 0; p < 8; p++) {
        int idx = p * 256 + t;           // 0..2047
        int h = idx >> 8, k = idx & 255;
        float s = 0.f;
#pragma unroll
        for (int d = 0; d < DD; d++)
            s += Wm[(h * EMB + k) * DD + d] * (qm[h * 2 * DD + d] + qm[h * 2 * DD + DD + d]);
        g_v[idx] = s;
    }
    if (t < HH) {
        float s = 0.f;
#pragma unroll
        for (int d = 0; d < DD; d++)
            s += bm[t * DD + d] * (qm[t * 2 * DD + d] + qm[t * 2 * DD + DD + d]);
        g_cb[t] = s + qbm[t];
    }
}

// ---------------- K3c2: c2[b][h][i] from h1 . v[h] ----------------
// grid (128, 16), warp per row, 8 head-accumulators per lane.
__global__ __launch_bounds__(256) void k3_c2()
{
    int b = blockIdx.y;
    int w = threadIdx.x >> 5, lane = threadIdx.x & 31;
    int i = blockIdx.x * 8 + w;
    const float* h1p = g_h1 + ((size_t)(b * NN + i)) * EMB;

    float s[HH];
#pragma unroll
    for (int h = 0; h < HH; h++) s[h] = 0.f;

#pragma unroll
    for (int kk = 0; kk < EMB / 32; kk++) {
        int k = kk * 32 + lane;
        float hv = h1p[k];
#pragma unroll
        for (int h = 0; h < HH; h++) s[h] += hv * g_v[h * EMB + k];
    }
#pragma unroll
    for (int h = 0; h < HH; h++)
#pragma unroll
        for (int off = 16; off; off >>= 1)
            s[h] += __shfl_xor_sync(0xffffffffu, s[h], off);

    if (lane == 0) {
#pragma unroll
        for (int h = 0; h < HH; h++) {
            float sv = s[h] + g_cb[h];
            g_c2[(b * HH + h) * NN + i] = sv > 0.f ? sv : 0.01f * sv;
        }
    }
}

// ---------------- K4: Zinv rows for layer 2; also zero g_g ----------------
// grid (128, 16), 256 thr = 8 warps = 8 rows per CTA.
__global__ __launch_bounds__(256) void k4_zrow(const float* __restrict__ adj)
{
    int b = blockIdx.y;
    if (threadIdx.x < 64)
        g_g[b * (HH * NN) + blockIdx.x * 64 + threadIdx.x] = 0.f;

    int w = threadIdx.x >> 5, lane = threadIdx.x & 31;
    int i = blockIdx.x * 8 + w;

    float cc[HH];
#pragma unroll
    for (int h = 0; h < HH; h++) cc[h] = g_c2[(b * HH + h) * NN + i];

    const float* row = adj + ((size_t)(b * NN + i)) * NN;
    float s[HH];
#pragma unroll
    for (int h = 0; h < HH; h++) s[h] = 0.f;

#pragma unroll 4
    for (int j = lane; j < NN; j += 32) {
        float a = row[j];
#pragma unroll
        for (int h = 0; h < HH; h++) s[h] += __expf(cc[h] * a);
    }
#pragma unroll
    for (int h = 0; h < HH; h++)
#pragma unroll
        for (int off = 16; off; off >>= 1)
            s[h] += __shfl_xor_sync(0xffffffffu, s[h], off);

    if (lane == 0) {
#pragma unroll
        for (int h = 0; h < HH; h++)
            g_zi[(b * HH + h) * NN + i] = 1.f / s[h];
    }
}

// ---------------- K5a: g[b][h][j] += sum_i exp(c_i*adj_ij)*zinv_i ----------------
// grid (4 jblk, 4 iblk, 16 b), 256 thr; thread owns column j0+t.
__global__ __launch_bounds__(256) void k5a_colsum(const float* __restrict__ adj)
{
    __shared__ float c_s[HH][256];
    __shared__ float z_s[HH][256];
    int b = blockIdx.z, j0 = blockIdx.x * 256, i0 = blockIdx.y * 256;
    int t = threadIdx.x;
#pragma unroll
    for (int h = 0; h < HH; h++) {
        c_s[h][t] = g_c2[(b * HH + h) * NN + i0 + t];
        z_s[h][t] = g_zi[(b * HH + h) * NN + i0 + t];
    }
    __syncthreads();

    float gacc[HH];
#pragma unroll
    for (int h = 0; h < HH; h++) gacc[h] = 0.f;

    const float* col = adj + (size_t)b * NN * NN + (size_t)i0 * NN + j0 + t;
#pragma unroll 4
    for (int i = 0; i < 256; i++) {
        float a = col[(size_t)i * NN];
#pragma unroll
        for (int h = 0; h < HH; h++)
            gacc[h] += __expf(c_s[h][i] * a) * z_s[h][i];
    }
#pragma unroll
    for (int h = 0; h < HH; h++)
        atomicAdd(&g_g[(b * HH + h) * NN + j0 + t], gacc[h]);
}

// ---------------- K5b: u = sum_j g_j * h1_j ; p = u@Wm + 1024*bm ----------------
// grid (8 h, 16 b), 256 thr.
__global__ __launch_bounds__(256) void k5b_pool(
    const float* __restrict__ Wm, const float* __restrict__ bm)
{
    __shared__ float g_sm[NN];
    __shared__ float u_s[EMB];
    __shared__ float red[8][32];
    int b = blockIdx.y, h = blockIdx.x;
    int t = threadIdx.x;

#pragma unroll
    for (int p = 0; p < 4; p++)
        g_sm[p * 256 + t] = g_g[(b * HH + h) * NN + p * 256 + t];
    __syncthreads();

    float u = 0.f;
    const float* h1p = g_h1 + (size_t)b * NN * EMB + t;
#pragma unroll 4
    for (int j = 0; j < NN; j++)
        u += g_sm[j] * h1p[(size_t)j * EMB];
    u_s[t] = u;
    __syncthreads();

    int d = t & 31, slice = t >> 5;
    const float* wm = Wm + h * EMB * DD;
    float acc = 0.f;
#pragma unroll
    for (int kk = 0; kk < 32; kk++) {
        int k = slice * 32 + kk;
        acc += u_s[k] * wm[k * DD + d];
    }
    red[slice][d] = acc;
    __syncthreads();
    if (t < 32) {
        float s = 0.f;
#pragma unroll
        for (int sl = 0; sl < 8; sl++) s += red[sl][t];
        g_p[b * EMB + h * DD + t] = s + 1024.f * bm[h * DD + t];
    }
}

// ---------------- K6: final MLP head ----------------
__global__ __launch_bounds__(256) void k6_mlp(
    const float* __restrict__ Wp, const float* __restrict__ bp,
    const float* __restrict__ gamma, const float* __restrict__ beta,
    const float* __restrict__ rmean, const float* __restrict__ rvar,
    const float* __restrict__ W1, const float* __restrict__ b1,
    const float* __restrict__ W2, const float* __restrict__ b2,
    float* __restrict__ out)
{
    __shared__ float p_s[256];
    __shared__ float y_s[512];
    __shared__ float z_s[256];
    __shared__ float w_s[128];
    int b = blockIdx.x, t = threadIdx.x;

    p_s[t] = g_p[b * EMB + t];
    __syncthreads();

#pragma unroll
    for (int r = 0; r < 2; r++) {
        int o = r * 256 + t;
        float acc = bp[o];
#pragma unroll 4
        for (int k = 0; k < 256; k++) acc += p_s[k] * Wp[k * 512 + o];
        acc = (acc - rmean[o]) * rsqrtf(rvar[o] + 1e-5f) * gamma[o] + beta[o];
        y_s[o] = fmaxf(acc, 0.f);
    }
    __syncthreads();
    {
        float acc = b1[t];
#pragma unroll 4
        for (int k = 0; k < 512; k++) acc += y_s[k] * W1[k * 256 + t];
        z_s[t] = fmaxf(acc, 0.f);
    }
    __syncthreads();
    if (t < 128) {
        float acc = b2[t];
#pragma unroll 4
        for (int k = 0; k < 256; k++) acc += z_s[k] * W2[k * 128 + t];
        w_s[t] = fmaxf(acc, 0.f);
    }
    __syncthreads();
    if (t < 64) w_s[t] += w_s[t + 64];
    __syncthreads();
    if (t < 32) {
        float v = w_s[t] + w_s[t + 32];
#pragma unroll
        for (int off = 16; off; off >>= 1) v += __shfl_xor_sync(0xffffffffu, v, off);
        if (t == 0) out[b] = v * (1.f / 128.f);
    }
}

// ---------------- launch ----------------
extern "C" void kernel_launch(void* const* d_in, const int* in_sizes, int n_in,
                              void* d_out, int out_size)
{
    const float* x     = (const float*)d_in[0];
    const float* adj   = (const float*)d_in[1];
    const float* Ws    = (const float*)d_in[2];
    const float* bs    = (const float*)d_in[3];
    const float* qs    = (const float*)d_in[4];
    const float* qbs   = (const float*)d_in[5];
    const float* Wm    = (const float*)d_in[6];
    const float* bm    = (const float*)d_in[7];
    const float* qm    = (const float*)d_in[8];
    const float* qbm   = (const float*)d_in[9];
    const float* Wp    = (const float*)d_in[10];
    const float* bp    = (const float*)d_in[11];
    const float* gamma = (const float*)d_in[12];
    const float* beta  = (const float*)d_in[13];
    const float* rmean = (const float*)d_in[14];
    const float* rvar  = (const float*)d_in[15];
    const float* W1    = (const float*)d_in[16];
    const float* b1    = (const float*)d_in[17];
    const float* W2    = (const float*)d_in[18];
    const float* b2    = (const float*)d_in[19];
    float* out = (float*)d_out;

    k1_wh1<<<(BB * HH * NN) / 256, 256>>>(x, Ws, bs, qs, qbs);
    k2_attn1<<<dim3(HH, NN / 128, BB), 128>>>(adj);
    k3v<<<1, 256>>>(Wm, bm, qm, qbm);
    k3_c2<<<dim3(NN / 8, BB), 256>>>();
    k4_zrow<<<dim3(NN / 8, BB), 256>>>(adj);
    k5a_colsum<<<dim3(4, 4, BB), 256>>>(adj);
    k5b_pool<<<dim3(HH, BB), 256>>>(Wm, bm);
    k6_mlp<<<BB, 256>>>(Wp, bp, gamma, beta, rmean, rvar, W1, b1, W2, b2, out);
}

// round 3
// speedup vs baseline: 1.5464x; 1.5464x over previous
#include <cuda_runtime.h>
#include <cstdint>
#include <cstddef>

// Shapes
#define BB   16
#define NN   1024
#define FIN  7
#define HH   8
#define DD   32
#define EMB  256

// ---------------- scratch ----------------
__device__ float g_WhT[BB * HH * DD * NN];   // [b][h][d][n] 16 MB, tf32-rounded
__device__ float g_c1 [BB * HH * NN];
__device__ float g_h1 [BB * NN * EMB];       // [b][n][h*32+d] 16 MB
__device__ float g_c2 [BB * HH * NN];
__device__ float g_zi [BB * HH * NN];
__device__ float g_g  [BB * HH * NN];
__device__ float g_v  [HH * EMB];
__device__ float g_cb [HH];
__device__ float g_p  [BB * EMB];

// ---------------- helpers ----------------
__device__ __forceinline__ uint32_t smem_u32(const void* p) {
    uint32_t a;
    asm("{ .reg .u64 t; cvta.to.shared.u64 t, %1; cvt.u32.u64 %0, t; }" : "=r"(a) : "l"(p));
    return a;
}
__device__ __forceinline__ uint32_t cvt_tf32(float f) {
    uint32_t r; asm("cvt.rna.tf32.f32 %0, %1;" : "=r"(r) : "f"(f)); return r;
}
__device__ __forceinline__ float ex2f(float x) {
    float r; asm("ex2.approx.f32 %0, %1;" : "=f"(r) : "f"(x)); return r;
}
#define LOG2E 1.4426950408889634f

#define CP_ASYNC16(dst, src) \
    asm volatile("cp.async.cg.shared.global [%0], [%1], 16;" :: "r"(dst), "l"(src) : "memory")
#define CP_COMMIT() asm volatile("cp.async.commit_group;" ::: "memory")
#define CP_WAIT(n)  asm volatile("cp.async.wait_group %0;" :: "n"(n) : "memory")

#define MMA_TF32(c, a0, a1, a2, a3, b0, b1) \
    asm volatile("mma.sync.aligned.m16n8k8.row.col.f32.tf32.tf32.f32 " \
        "{%0,%1,%2,%3}, {%4,%5,%6,%7}, {%8,%9}, {%0,%1,%2,%3};" \
        : "+f"((c)[0]), "+f"((c)[1]), "+f"((c)[2]), "+f"((c)[3]) \
        : "r"(a0), "r"(a1), "r"(a2), "r"(a3), "r"(b0), "r"(b1))

// ---------------- K1: WhT = tf32_round((x@Ws + bs)^T); c1 ----------------
__global__ __launch_bounds__(256) void k1_wh1(
    const float* __restrict__ x,  const float* __restrict__ Ws,
    const float* __restrict__ bs, const float* __restrict__ qs,
    const float* __restrict__ qbs)
{
    int idx = blockIdx.x * blockDim.x + threadIdx.x;
    int n = idx & (NN - 1);
    int h = (idx >> 10) & (HH - 1);
    int b = idx >> 13;

    float xv[FIN];
    const float* xr = x + ((size_t)(b * NN + n)) * FIN;
#pragma unroll
    for (int i = 0; i < FIN; i++) xv[i] = xr[i];

    const float* W = Ws + h * FIN * DD;
    float s = qbs[h];
    float* outT = g_WhT + ((size_t)(b * HH + h) * DD) * NN + n;
#pragma unroll
    for (int d = 0; d < DD; d++) {
        float acc = bs[h * DD + d];
#pragma unroll
        for (int i = 0; i < FIN; i++) acc += xv[i] * W[i * DD + d];
        outT[(size_t)d * NN] = __uint_as_float(cvt_tf32(acc));
        s += acc * (qs[h * 2 * DD + d] + qs[h * 2 * DD + DD + d]);
    }
    g_c1[idx] = s > 0.f ? s : 0.01f * s;
}

// ---------------- K2: layer-1 attention via mma.sync tf32 ----------------
// CTA = (64-row i-block, b), 256 thr, warp = head. Warp tile M=64, N=32, K=1024.
// E generated in A-fragment registers: E = ex2(c*log2e * adj), tf32-rounded.
__global__ __launch_bounds__(256, 2) void k2_mma(const float* __restrict__ adj)
{
    __shared__ float adj_s[2][64 * 68];   // stride 68: conflict-free frag reads

    int t = threadIdx.x;
    int lane = t & 31, h = t >> 5;         // warp index == head
    int gid = lane >> 2, tig = lane & 3;
    int i0 = blockIdx.x * 64, b = blockIdx.y;

    const float* adjb = adj + (size_t)b * NN * NN;
    const float* whT  = g_WhT + (size_t)((b * HH + h) * DD) * NN;
    const float* c1p  = g_c1 + (b * HH + h) * NN + i0;

    float cl[4][2];
#pragma unroll
    for (int mt = 0; mt < 4; mt++) {
        cl[mt][0] = c1p[mt * 16 + gid]     * LOG2E;
        cl[mt][1] = c1p[mt * 16 + gid + 8] * LOG2E;
    }

    float acc[4][4][4];
    float z0[4], z1[4];
#pragma unroll
    for (int mt = 0; mt < 4; mt++) {
        z0[mt] = 0.f; z1[mt] = 0.f;
#pragma unroll
        for (int nt = 0; nt < 4; nt++)
#pragma unroll
            for (int r = 0; r < 4; r++) acc[mt][nt][r] = 0.f;
    }

    uint32_t sbase = smem_u32(adj_s);

    // prefetch tile -> buf (64 rows x 64 floats, cp.async 16B)
#define PREFETCH(tile, buf) do { \
        uint32_t dst0 = sbase + (buf) * (64 * 68 * 4); \
        const float* srcb = adjb + (size_t)i0 * NN + (tile) * 64; \
        _Pragma("unroll") \
        for (int p = 0; p < 4; p++) { \
            int idx = p * 256 + t; \
            int row = idx >> 4, f4 = idx & 15; \
            CP_ASYNC16(dst0 + (row * 68 + f4 * 4) * 4, \
                       srcb + (size_t)row * NN + f4 * 4); \
        } \
        CP_COMMIT(); \
    } while (0)

    PREFETCH(0, 0);

#pragma unroll 1
    for (int tile = 0; tile < 16; tile++) {
        if (tile + 1 < 16) { PREFETCH(tile + 1, (tile + 1) & 1); CP_WAIT(1); }
        else               { CP_WAIT(0); }
        __syncthreads();
        const float* As = adj_s[tile & 1];

#pragma unroll
        for (int ks = 0; ks < 8; ks++) {
            int kg = tile * 64 + ks * 8;
            // B fragments: d = nt*8 + gid, k = kg + tig (+4). WhT pre-rounded tf32.
            uint32_t bw[4][2];
            const float* Bp = whT + (size_t)gid * NN + kg + tig;
#pragma unroll
            for (int nt = 0; nt < 4; nt++) {
                bw[nt][0] = __float_as_uint(__ldg(Bp + (size_t)nt * 8 * NN));
                bw[nt][1] = __float_as_uint(__ldg(Bp + (size_t)nt * 8 * NN + 4));
            }
#pragma unroll
            for (int mt = 0; mt < 4; mt++) {
                int rb = mt * 16 + gid;
                float r0 = As[rb * 68 + ks * 8 + tig];
                float r1 = As[(rb + 8) * 68 + ks * 8 + tig];
                float r2 = As[rb * 68 + ks * 8 + tig + 4];
                float r3 = As[(rb + 8) * 68 + ks * 8 + tig + 4];
                uint32_t a0 = cvt_tf32(ex2f(cl[mt][0] * r0));
                uint32_t a1 = cvt_tf32(ex2f(cl[mt][1] * r1));
                uint32_t a2 = cvt_tf32(ex2f(cl[mt][0] * r2));
                uint32_t a3 = cvt_tf32(ex2f(cl[mt][1] * r3));
                z0[mt] += __uint_as_float(a0) + __uint_as_float(a2);
                z1[mt] += __uint_as_float(a1) + __uint_as_float(a3);
#pragma unroll
                for (int nt = 0; nt < 4; nt++)
                    MMA_TF32(acc[mt][nt], a0, a1, a2, a3, bw[nt][0], bw[nt][1]);
            }
        }
        __syncthreads();
    }

    // Z: reduce over tig (lanes xor 1, 2)
#pragma unroll
    for (int mt = 0; mt < 4; mt++) {
        z0[mt] += __shfl_xor_sync(0xffffffffu, z0[mt], 1);
        z0[mt] += __shfl_xor_sync(0xffffffffu, z0[mt], 2);
        z1[mt] += __shfl_xor_sync(0xffffffffu, z1[mt], 1);
        z1[mt] += __shfl_xor_sync(0xffffffffu, z1[mt], 2);
    }

#pragma unroll
    for (int mt = 0; mt < 4; mt++) {
        float zi0 = 1.f / z0[mt], zi1 = 1.f / z1[mt];
        float* o0 = g_h1 + ((size_t)(b * NN + i0 + mt * 16 + gid)) * EMB + h * 32;
        float* o1 = o0 + (size_t)8 * EMB;
#pragma unroll
        for (int nt = 0; nt < 4; nt++) {
            *(float2*)(o0 + nt * 8 + tig * 2) =
                make_float2(acc[mt][nt][0] * zi0, acc[mt][nt][1] * zi0);
            *(float2*)(o1 + nt * 8 + tig * 2) =
                make_float2(acc[mt][nt][2] * zi1, acc[mt][nt][3] * zi1);
        }
    }
}

// ---------------- K3v ----------------
__global__ __launch_bounds__(256) void k3v(
    const float* __restrict__ Wm, const float* __restrict__ bm,
    const float* __restrict__ qm, const float* __restrict__ qbm)
{
    int t = threadIdx.x;
#pragma unroll
    for (int p = 0; p < 8; p++) {
        int idx = p * 256 + t;
        int h = idx >> 8, k = idx & 255;
        float s = 0.f;
#pragma unroll
        for (int d = 0; d < DD; d++)
            s += Wm[(h * EMB + k) * DD + d] * (qm[h * 2 * DD + d] + qm[h * 2 * DD + DD + d]);
        g_v[idx] = s;
    }
    if (t < HH) {
        float s = 0.f;
#pragma unroll
        for (int d = 0; d < DD; d++)
            s += bm[t * DD + d] * (qm[t * 2 * DD + d] + qm[t * 2 * DD + DD + d]);
        g_cb[t] = s + qbm[t];
    }
}

// ---------------- K3c2 ----------------
__global__ __launch_bounds__(256) void k3_c2()
{
    int b = blockIdx.y;
    int w = threadIdx.x >> 5, lane = threadIdx.x & 31;
    int i = blockIdx.x * 8 + w;
    const float* h1p = g_h1 + ((size_t)(b * NN + i)) * EMB;

    float s[HH];
#pragma unroll
    for (int h = 0; h < HH; h++) s[h] = 0.f;
#pragma unroll
    for (int kk = 0; kk < EMB / 32; kk++) {
        int k = kk * 32 + lane;
        float hv = h1p[k];
#pragma unroll
        for (int h = 0; h < HH; h++) s[h] += hv * g_v[h * EMB + k];
    }
#pragma unroll
    for (int h = 0; h < HH; h++)
#pragma unroll
        for (int off = 16; off; off >>= 1)
            s[h] += __shfl_xor_sync(0xffffffffu, s[h], off);
    if (lane == 0) {
#pragma unroll
        for (int h = 0; h < HH; h++) {
            float sv = s[h] + g_cb[h];
            g_c2[(b * HH + h) * NN + i] = sv > 0.f ? sv : 0.01f * sv;
        }
    }
}

// ---------------- K4 ----------------
__global__ __launch_bounds__(256) void k4_zrow(const float* __restrict__ adj)
{
    int b = blockIdx.y;
    if (threadIdx.x < 64)
        g_g[b * (HH * NN) + blockIdx.x * 64 + threadIdx.x] = 0.f;

    int w = threadIdx.x >> 5, lane = threadIdx.x & 31;
    int i = blockIdx.x * 8 + w;

    float cc[HH];
#pragma unroll
    for (int h = 0; h < HH; h++) cc[h] = g_c2[(b * HH + h) * NN + i];

    const float* row = adj + ((size_t)(b * NN + i)) * NN;
    float s[HH];
#pragma unroll
    for (int h = 0; h < HH; h++) s[h] = 0.f;
#pragma unroll 4
    for (int j = lane; j < NN; j += 32) {
        float a = row[j];
#pragma unroll
        for (int h = 0; h < HH; h++) s[h] += __expf(cc[h] * a);
    }
#pragma unroll
    for (int h = 0; h < HH; h++)
#pragma unroll
        for (int off = 16; off; off >>= 1)
            s[h] += __shfl_xor_sync(0xffffffffu, s[h], off);
    if (lane == 0) {
#pragma unroll
        for (int h = 0; h < HH; h++)
            g_zi[(b * HH + h) * NN + i] = 1.f / s[h];
    }
}

// ---------------- K5a ----------------
__global__ __launch_bounds__(256) void k5a_colsum(const float* __restrict__ adj)
{
    __shared__ float c_s[HH][256];
    __shared__ float z_s[HH][256];
    int b = blockIdx.z, j0 = blockIdx.x * 256, i0 = blockIdx.y * 256;
    int t = threadIdx.x;
#pragma unroll
    for (int h = 0; h < HH; h++) {
        c_s[h][t] = g_c2[(b * HH + h) * NN + i0 + t];
        z_s[h][t] = g_zi[(b * HH + h) * NN + i0 + t];
    }
    __syncthreads();

    float gacc[HH];
#pragma unroll
    for (int h = 0; h < HH; h++) gacc[h] = 0.f;

    const float* col = adj + (size_t)b * NN * NN + (size_t)i0 * NN + j0 + t;
#pragma unroll 4
    for (int i = 0; i < 256; i++) {
        float a = col[(size_t)i * NN];
#pragma unroll
        for (int h = 0; h < HH; h++)
            gacc[h] += __expf(c_s[h][i] * a) * z_s[h][i];
    }
#pragma unroll
    for (int h = 0; h < HH; h++)
        atomicAdd(&g_g[(b * HH + h) * NN + j0 + t], gacc[h]);
}

// ---------------- K5b ----------------
__global__ __launch_bounds__(256) void k5b_pool(
    const float* __restrict__ Wm, const float* __restrict__ bm)
{
    __shared__ float g_sm[NN];
    __shared__ float u_s[EMB];
    __shared__ float red[8][32];
    int b = blockIdx.y, h = blockIdx.x;
    int t = threadIdx.x;

#pragma unroll
    for (int p = 0; p < 4; p++)
        g_sm[p * 256 + t] = g_g[(b * HH + h) * NN + p * 256 + t];
    __syncthreads();

    float u = 0.f;
    const float* h1p = g_h1 + (size_t)b * NN * EMB + t;
#pragma unroll 4
    for (int j = 0; j < NN; j++)
        u += g_sm[j] * h1p[(size_t)j * EMB];
    u_s[t] = u;
    __syncthreads();

    int d = t & 31, slice = t >> 5;
    const float* wm = Wm + h * EMB * DD;
    float acc = 0.f;
#pragma unroll
    for (int kk = 0; kk < 32; kk++) {
        int k = slice * 32 + kk;
        acc += u_s[k] * wm[k * DD + d];
    }
    red[slice][d] = acc;
    __syncthreads();
    if (t < 32) {
        float s = 0.f;
#pragma unroll
        for (int sl = 0; sl < 8; sl++) s += red[sl][t];
        g_p[b * EMB + h * DD + t] = s + 1024.f * bm[h * DD + t];
    }
}

// ---------------- K6 ----------------
__global__ __launch_bounds__(256) void k6_mlp(
    const float* __restrict__ Wp, const float* __restrict__ bp,
    const float* __restrict__ gamma, const float* __restrict__ beta,
    const float* __restrict__ rmean, const float* __restrict__ rvar,
    const float* __restrict__ W1, const float* __restrict__ b1,
    const float* __restrict__ W2, const float* __restrict__ b2,
    float* __restrict__ out)
{
    __shared__ float p_s[256];
    __shared__ float y_s[512];
    __shared__ float z_s[256];
    __shared__ float w_s[128];
    int b = blockIdx.x, t = threadIdx.x;

    p_s[t] = g_p[b * EMB + t];
    __syncthreads();
#pragma unroll
    for (int r = 0; r < 2; r++) {
        int o = r * 256 + t;
        float acc = bp[o];
#pragma unroll 4
        for (int k = 0; k < 256; k++) acc += p_s[k] * Wp[k * 512 + o];
        acc = (acc - rmean[o]) * rsqrtf(rvar[o] + 1e-5f) * gamma[o] + beta[o];
        y_s[o] = fmaxf(acc, 0.f);
    }
    __syncthreads();
    {
        float acc = b1[t];
#pragma unroll 4
        for (int k = 0; k < 512; k++) acc += y_s[k] * W1[k * 256 + t];
        z_s[t] = fmaxf(acc, 0.f);
    }
    __syncthreads();
    if (t < 128) {
        float acc = b2[t];
#pragma unroll 4
        for (int k = 0; k < 256; k++) acc += z_s[k] * W2[k * 128 + t];
        w_s[t] = fmaxf(acc, 0.f);
    }
    __syncthreads();
    if (t < 64) w_s[t] += w_s[t + 64];
    __syncthreads();
    if (t < 32) {
        float v = w_s[t] + w_s[t + 32];
#pragma unroll
        for (int off = 16; off; off >>= 1) v += __shfl_xor_sync(0xffffffffu, v, off);
        if (t == 0) out[b] = v * (1.f / 128.f);
    }
}

// ---------------- launch ----------------
extern "C" void kernel_launch(void* const* d_in, const int* in_sizes, int n_in,
                              void* d_out, int out_size)
{
    const float* x     = (const float*)d_in[0];
    const float* adj   = (const float*)d_in[1];
    const float* Ws    = (const float*)d_in[2];
    const float* bs    = (const float*)d_in[3];
    const float* qs    = (const float*)d_in[4];
    const float* qbs   = (const float*)d_in[5];
    const float* Wm    = (const float*)d_in[6];
    const float* bm    = (const float*)d_in[7];
    const float* qm    = (const float*)d_in[8];
    const float* qbm   = (const float*)d_in[9];
    const float* Wp    = (const float*)d_in[10];
    const float* bp    = (const float*)d_in[11];
    const float* gamma = (const float*)d_in[12];
    const float* beta  = (const float*)d_in[13];
    const float* rmean = (const float*)d_in[14];
    const float* rvar  = (const float*)d_in[15];
    const float* W1    = (const float*)d_in[16];
    const float* b1    = (const float*)d_in[17];
    const float* W2    = (const float*)d_in[18];
    const float* b2    = (const float*)d_in[19];
    float* out = (float*)d_out;

    k1_wh1<<<(BB * HH * NN) / 256, 256>>>(x, Ws, bs, qs, qbs);
    k2_mma<<<dim3(NN / 64, BB), 256>>>(adj);
    k3v<<<1, 256>>>(Wm, bm, qm, qbm);
    k3_c2<<<dim3(NN / 8, BB), 256>>>();
    k4_zrow<<<dim3(NN / 8, BB), 256>>>(adj);
    k5a_colsum<<<dim3(4, 4, BB), 256>>>(adj);
    k5b_pool<<<dim3(HH, BB), 256>>>(Wm, bm);
    k6_mlp<<<BB, 256>>>(Wp, bp, gamma, beta, rmean, rvar, W1, b1, W2, b2, out);
}

// round 4
// speedup vs baseline: 1.7372x; 1.1233x over previous
#include <cuda_runtime.h>
#include <cuda_fp16.h>
#include <cstdint>
#include <cstddef>

// Shapes
#define BB   16
#define NN   1024
#define FIN  7
#define HH   8
#define DD   32
#define EMB  256
#define LOG2E 1.4426950408889634f

// ---------------- scratch ----------------
__device__ __half g_WhTh[BB * HH * DD * NN];  // [b][h][d][n] half, 8 MB
__device__ float g_c1 [BB * HH * NN];
__device__ float g_h1 [BB * NN * EMB];        // [b][n][h*32+d] 16 MB
__device__ float g_c2 [BB * HH * NN];         // k2 atomically accumulates h1.v
__device__ float g_zi [BB * HH * NN];
__device__ float g_g  [BB * HH * NN];
__device__ float g_v  [HH * EMB];
__device__ float g_cb [HH];
__device__ float g_p  [BB * EMB];

// ---------------- half2 helpers (uint32-carried) ----------------
__device__ __forceinline__ uint32_t h2exp2_u(uint32_t x) {
    uint32_t r; asm("ex2.approx.f16x2 %0, %1;" : "=r"(r) : "r"(x)); return r;
}
__device__ __forceinline__ uint32_t h2mul_u(uint32_t a, uint32_t b) {
    uint32_t r; asm("mul.f16x2 %0, %1, %2;" : "=r"(r) : "r"(a), "r"(b)); return r;
}
__device__ __forceinline__ uint32_t h2add_u(uint32_t a, uint32_t b) {
    uint32_t r; asm("add.f16x2 %0, %1, %2;" : "=r"(r) : "r"(a), "r"(b)); return r;
}
// pack {lo, hi} floats -> half2
__device__ __forceinline__ uint32_t f22h2_u(float hi, float lo) {
    uint32_t r; asm("cvt.rn.f16x2.f32 %0, %1, %2;" : "=r"(r) : "f"(hi), "f"(lo)); return r;
}
// broadcast one float to both halves
__device__ __forceinline__ uint32_t f2h2b(float a) {
    uint32_t r;
    asm("{ .reg .f16 v; cvt.rn.f16.f32 v, %1; mov.b32 %0, {v, v}; }" : "=r"(r) : "f"(a));
    return r;
}
__device__ __forceinline__ float2 h22f2(uint32_t h) {
    float2 f;
    asm("{ .reg .f16 l, hh; mov.b32 {l, hh}, %2; cvt.f32.f16 %0, l; cvt.f32.f16 %1, hh; }"
        : "=f"(f.x), "=f"(f.y) : "r"(h));
    return f;
}

#define CP_ASYNC16(dst, src) \
    asm volatile("cp.async.cg.shared.global [%0], [%1], 16;" :: "r"(dst), "l"(src) : "memory")
#define CP_COMMIT() asm volatile("cp.async.commit_group;" ::: "memory")
#define CP_WAIT(n)  asm volatile("cp.async.wait_group %0;" :: "n"(n) : "memory")

#define MMA_F16(c, a0, a1, a2, a3, b0, b1) \
    asm volatile("mma.sync.aligned.m16n8k16.row.col.f32.f16.f16.f32 " \
        "{%0,%1,%2,%3}, {%4,%5,%6,%7}, {%8,%9}, {%0,%1,%2,%3};" \
        : "+f"((c)[0]), "+f"((c)[1]), "+f"((c)[2]), "+f"((c)[3]) \
        : "r"(a0), "r"(a1), "r"(a2), "r"(a3), "r"(b0), "r"(b1))

__device__ __forceinline__ uint32_t smem_u32(const void* p) {
    uint32_t a;
    asm("{ .reg .u64 t; cvta.to.shared.u64 t, %1; cvt.u32.u64 %0, t; }" : "=r"(a) : "l"(p));
    return a;
}

// ---------------- K1: WhTh = half((x@Ws + bs)^T); c1; zero c2 ----------------
__global__ __launch_bounds__(256) void k1_wh1(
    const float* __restrict__ x,  const float* __restrict__ Ws,
    const float* __restrict__ bs, const float* __restrict__ qs,
    const float* __restrict__ qbs)
{
    int idx = blockIdx.x * blockDim.x + threadIdx.x;
    int n = idx & (NN - 1);
    int h = (idx >> 10) & (HH - 1);
    int b = idx >> 13;

    g_c2[idx] = 0.f;   // zero accumulator for fused c2 atomics

    float xv[FIN];
    const float* xr = x + ((size_t)(b * NN + n)) * FIN;
#pragma unroll
    for (int i = 0; i < FIN; i++) xv[i] = xr[i];

    const float* W = Ws + h * FIN * DD;
    float s = qbs[h];
    __half* outT = g_WhTh + ((size_t)(b * HH + h) * DD) * NN + n;
#pragma unroll
    for (int d = 0; d < DD; d++) {
        float acc = bs[h * DD + d];
#pragma unroll
        for (int i = 0; i < FIN; i++) acc += xv[i] * W[i * DD + d];
        outT[(size_t)d * NN] = __float2half_rn(acc);
        s += acc * (qs[h * 2 * DD + d] + qs[h * 2 * DD + DD + d]);
    }
    g_c1[idx] = s > 0.f ? s : 0.01f * s;
}

// ---------------- K3v: v[h][k], cb[h] (runs BEFORE k2) ----------------
__global__ __launch_bounds__(256) void k3v(
    const float* __restrict__ Wm, const float* __restrict__ bm,
    const float* __restrict__ qm, const float* __restrict__ qbm)
{
    int t = threadIdx.x;
#pragma unroll
    for (int p = 0; p < 8; p++) {
        int idx = p * 256 + t;
        int h = idx >> 8, k = idx & 255;
        float s = 0.f;
#pragma unroll
        for (int d = 0; d < DD; d++)
            s += Wm[(h * EMB + k) * DD + d] * (qm[h * 2 * DD + d] + qm[h * 2 * DD + DD + d]);
        g_v[idx] = s;
    }
    if (t < HH) {
        float s = 0.f;
#pragma unroll
        for (int d = 0; d < DD; d++)
            s += bm[t * DD + d] * (qm[t * 2 * DD + d] + qm[t * 2 * DD + DD + d]);
        g_cb[t] = s + qbm[t];
    }
}

// ---------------- K2: layer-1 attention via mma.sync f16 m16n8k16 ----------------
// CTA = (64-row i-block, b), 256 thr, warp = head. Warp tile M=64, N=32(+Z col), K=1024.
// E built in A-fragment regs: half2(exp2(cl*adj)). Z accumulated by ones-column MMA.
// Epilogue also accumulates c2 partial dots (h1 . v) via atomics.
__global__ __launch_bounds__(256, 2) void k2_mma(const float* __restrict__ adj)
{
    __shared__ float adj_s[2][64 * 72];   // stride 72: conflict-free LDS.64
    __shared__ float v_s[HH * EMB];       // 8 KB

    int t = threadIdx.x;
    int lane = t & 31, h = t >> 5;         // warp index == source head
    int gid = lane >> 2, tig = lane & 3;
    int i0 = blockIdx.x * 64, b = blockIdx.y;

#pragma unroll
    for (int p = 0; p < 8; p++) v_s[p * 256 + t] = g_v[p * 256 + t];

    const float* adjb = adj + (size_t)b * NN * NN;
    const __half* whT = g_WhTh + (size_t)((b * HH + h) * DD) * NN;
    const float* c1p  = g_c1 + (b * HH + h) * NN + i0;

    uint32_t clb[4][2];   // broadcast half2 of c*log2e for rows gid, gid+8 per mt
#pragma unroll
    for (int mt = 0; mt < 4; mt++) {
        clb[mt][0] = f2h2b(c1p[mt * 16 + gid]     * LOG2E);
        clb[mt][1] = f2h2b(c1p[mt * 16 + gid + 8] * LOG2E);
    }
    uint32_t bz = (gid == 0) ? 0x3C003C00u : 0u;   // ones column B fragment

    float acc[4][4][4];
    float accz[4][4];
#pragma unroll
    for (int mt = 0; mt < 4; mt++) {
#pragma unroll
        for (int r = 0; r < 4; r++) accz[mt][r] = 0.f;
#pragma unroll
        for (int nt = 0; nt < 4; nt++)
#pragma unroll
            for (int r = 0; r < 4; r++) acc[mt][nt][r] = 0.f;
    }

    uint32_t sbase = smem_u32(adj_s);

#define PREFETCH(tile, buf) do { \
        uint32_t dst0 = sbase + (buf) * (64 * 72 * 4); \
        const float* srcb = adjb + (size_t)i0 * NN + (tile) * 64; \
        _Pragma("unroll") \
        for (int p = 0; p < 4; p++) { \
            int idx = p * 256 + t; \
            int row = idx >> 4, f4 = idx & 15; \
            CP_ASYNC16(dst0 + (row * 72 + f4 * 4) * 4, \
                       srcb + (size_t)row * NN + f4 * 4); \
        } \
        CP_COMMIT(); \
    } while (0)

    PREFETCH(0, 0);

#pragma unroll 1
    for (int tile = 0; tile < 16; tile++) {
        if (tile + 1 < 16) { PREFETCH(tile + 1, (tile + 1) & 1); CP_WAIT(1); }
        else               { CP_WAIT(0); }
        __syncthreads();
        const float* As = adj_s[tile & 1];

#pragma unroll
        for (int ks = 0; ks < 4; ks++) {
            int kg = tile * 64 + ks * 16;
            // B fragments: rows d = nt*8+gid of WhTh, k = kg+2tig (+1), +8 (+9)
            uint32_t b0[4], b1[4];
            const __half* Bp = whT + (size_t)gid * NN + kg + 2 * tig;
#pragma unroll
            for (int nt = 0; nt < 4; nt++) {
                b0[nt] = *(const uint32_t*)(Bp + (size_t)nt * 8 * NN);
                b1[nt] = *(const uint32_t*)(Bp + (size_t)nt * 8 * NN + 8);
            }
#pragma unroll
            for (int mt = 0; mt < 4; mt++) {
                int rb = mt * 16 + gid;
                const float* base = As + ks * 16 + 2 * tig;
                float2 rl0 = *(const float2*)(base + rb * 72);
                float2 rl1 = *(const float2*)(base + (rb + 8) * 72);
                float2 rh0 = *(const float2*)(base + rb * 72 + 8);
                float2 rh1 = *(const float2*)(base + (rb + 8) * 72 + 8);
                uint32_t a0 = h2exp2_u(h2mul_u(clb[mt][0], f22h2_u(rl0.y, rl0.x)));
                uint32_t a1 = h2exp2_u(h2mul_u(clb[mt][1], f22h2_u(rl1.y, rl1.x)));
                uint32_t a2 = h2exp2_u(h2mul_u(clb[mt][0], f22h2_u(rh0.y, rh0.x)));
                uint32_t a3 = h2exp2_u(h2mul_u(clb[mt][1], f22h2_u(rh1.y, rh1.x)));
                MMA_F16(accz[mt], a0, a1, a2, a3, bz, bz);
#pragma unroll
                for (int nt = 0; nt < 4; nt++)
                    MMA_F16(acc[mt][nt], a0, a1, a2, a3, b0[nt], b1[nt]);
            }
        }
        __syncthreads();
    }

    // epilogue: per mt -> scale by 1/Z, store h1, accumulate c2 partial dots
#pragma unroll
    for (int mt = 0; mt < 4; mt++) {
        float z0 = __shfl_sync(0xffffffffu, accz[mt][0], lane & ~3);
        float z1 = __shfl_sync(0xffffffffu, accz[mt][2], lane & ~3);
        float zi0 = 1.f / z0, zi1 = 1.f / z1;

        int r0 = i0 + mt * 16 + gid;
        float* o0 = g_h1 + ((size_t)(b * NN + r0)) * EMB + h * 32;
        float* o1 = o0 + (size_t)8 * EMB;
        float q0[4][2], q1[4][2];
#pragma unroll
        for (int nt = 0; nt < 4; nt++) {
            q0[nt][0] = acc[mt][nt][0] * zi0; q0[nt][1] = acc[mt][nt][1] * zi0;
            q1[nt][0] = acc[mt][nt][2] * zi1; q1[nt][1] = acc[mt][nt][3] * zi1;
            *(float2*)(o0 + nt * 8 + 2 * tig) = make_float2(q0[nt][0], q0[nt][1]);
            *(float2*)(o1 + nt * 8 + 2 * tig) = make_float2(q1[nt][0], q1[nt][1]);
        }
        // c2 partials: for each target head th, dot this head's 32-dim chunk with v
#pragma unroll
        for (int th = 0; th < HH; th++) {
            float p0 = 0.f, p1 = 0.f;
#pragma unroll
            for (int nt = 0; nt < 4; nt++) {
                float2 vv = *(const float2*)&v_s[th * 256 + h * 32 + nt * 8 + 2 * tig];
                p0 += q0[nt][0] * vv.x + q0[nt][1] * vv.y;
                p1 += q1[nt][0] * vv.x + q1[nt][1] * vv.y;
            }
            p0 += __shfl_xor_sync(0xffffffffu, p0, 1);
            p0 += __shfl_xor_sync(0xffffffffu, p0, 2);
            p1 += __shfl_xor_sync(0xffffffffu, p1, 1);
            p1 += __shfl_xor_sync(0xffffffffu, p1, 2);
            if (tig == 0) {
                atomicAdd(&g_c2[(b * HH + th) * NN + r0], p0);
                atomicAdd(&g_c2[(b * HH + th) * NN + r0 + 8], p1);
            }
        }
    }
#undef PREFETCH
}

// ---------------- K4: finalize c2 (bias+leaky, writeback); Z rows (f16x2); zero g_g ----------------
__global__ __launch_bounds__(256) void k4_zrow(const float* __restrict__ adj)
{
    int b = blockIdx.y;
    if (threadIdx.x < 64)
        g_g[b * (HH * NN) + blockIdx.x * 64 + threadIdx.x] = 0.f;

    int w = threadIdx.x >> 5, lane = threadIdx.x & 31;
    int i = blockIdx.x * 8 + w;

    float c[HH];
#pragma unroll
    for (int h = 0; h < HH; h++) {
        float raw = g_c2[(b * HH + h) * NN + i] + g_cb[h];
        c[h] = raw > 0.f ? raw : 0.01f * raw;
    }
    if (lane == 0) {
#pragma unroll
        for (int h = 0; h < HH; h++) g_c2[(b * HH + h) * NN + i] = c[h];
    }
    uint32_t cl2[4];
#pragma unroll
    for (int p = 0; p < 4; p++)
        cl2[p] = f22h2_u(c[2 * p + 1] * LOG2E, c[2 * p] * LOG2E);

    const float* row = adj + ((size_t)(b * NN + i)) * NN;
    float s[HH];
#pragma unroll
    for (int h = 0; h < HH; h++) s[h] = 0.f;

#pragma unroll 1
    for (int jb = 0; jb < NN; jb += 256) {          // 8 elements per lane per chunk
        uint32_t acc2[4] = {0u, 0u, 0u, 0u};
#pragma unroll
        for (int jj = 0; jj < 8; jj++) {
            float a = row[jb + jj * 32 + lane];
            uint32_t ah = f2h2b(a);
#pragma unroll
            for (int p = 0; p < 4; p++)
                acc2[p] = h2add_u(acc2[p], h2exp2_u(h2mul_u(cl2[p], ah)));
        }
#pragma unroll
        for (int p = 0; p < 4; p++) {
            float2 f = h22f2(acc2[p]);
            s[2 * p] += f.x; s[2 * p + 1] += f.y;
        }
    }
#pragma unroll
    for (int h = 0; h < HH; h++)
#pragma unroll
        for (int off = 16; off; off >>= 1)
            s[h] += __shfl_xor_sync(0xffffffffu, s[h], off);
    if (lane == 0) {
#pragma unroll
        for (int h = 0; h < HH; h++)
            g_zi[(b * HH + h) * NN + i] = 1.f / s[h];
    }
}

// ---------------- K5a: g[j] += sum_i E_ij * zinv_i (f16x2) ----------------
__global__ __launch_bounds__(256) void k5a_colsum(const float* __restrict__ adj)
{
    __shared__ uint32_t ch2s[4][256];
    __shared__ uint32_t zi2s[4][256];
    int b = blockIdx.z, j0 = blockIdx.x * 256, i0 = blockIdx.y * 256;
    int t = threadIdx.x;
#pragma unroll
    for (int p = 0; p < 4; p++) {
        float c0 = g_c2[(b * HH + 2 * p)     * NN + i0 + t];
        float c1 = g_c2[(b * HH + 2 * p + 1) * NN + i0 + t];
        ch2s[p][t] = f22h2_u(c1 * LOG2E, c0 * LOG2E);
        float z0 = g_zi[(b * HH + 2 * p)     * NN + i0 + t];
        float z1 = g_zi[(b * HH + 2 * p + 1) * NN + i0 + t];
        zi2s[p][t] = f22h2_u(z1, z0);
    }
    __syncthreads();

    float gacc[HH];
#pragma unroll
    for (int h = 0; h < HH; h++) gacc[h] = 0.f;

    const float* col = adj + (size_t)b * NN * NN + (size_t)i0 * NN + j0 + t;
#pragma unroll 1
    for (int ib = 0; ib < 256; ib += 8) {
        uint32_t a2[4] = {0u, 0u, 0u, 0u};
#pragma unroll
        for (int jj = 0; jj < 8; jj++) {
            float a = col[(size_t)(ib + jj) * NN];
            uint32_t ah = f2h2b(a);
#pragma unroll
            for (int p = 0; p < 4; p++)
                a2[p] = h2add_u(a2[p],
                          h2mul_u(h2exp2_u(h2mul_u(ch2s[p][ib + jj], ah)),
                                  zi2s[p][ib + jj]));
        }
#pragma unroll
        for (int p = 0; p < 4; p++) {
            float2 f = h22f2(a2[p]);
            gacc[2 * p] += f.x; gacc[2 * p + 1] += f.y;
        }
    }
#pragma unroll
    for (int h = 0; h < HH; h++)
        atomicAdd(&g_g[(b * HH + h) * NN + j0 + t], gacc[h]);
}

// ---------------- K5b: u = sum_j g_j * h1_j ; p = u@Wm + 1024*bm ----------------
__global__ __launch_bounds__(256) void k5b_pool(
    const float* __restrict__ Wm, const float* __restrict__ bm)
{
    __shared__ float g_sm[NN];
    __shared__ float u_s[EMB];
    __shared__ float red[8][32];
    int b = blockIdx.y, h = blockIdx.x;
    int t = threadIdx.x;

#pragma unroll
    for (int p = 0; p < 4; p++)
        g_sm[p * 256 + t] = g_g[(b * HH + h) * NN + p * 256 + t];
    __syncthreads();

    float u = 0.f;
    const float* h1p = g_h1 + (size_t)b * NN * EMB + t;
#pragma unroll 4
    for (int j = 0; j < NN; j++)
        u += g_sm[j] * h1p[(size_t)j * EMB];
    u_s[t] = u;
    __syncthreads();

    int d = t & 31, slice = t >> 5;
    const float* wm = Wm + h * EMB * DD;
    float acc = 0.f;
#pragma unroll
    for (int kk = 0; kk < 32; kk++) {
        int k = slice * 32 + kk;
        acc += u_s[k] * wm[k * DD + d];
    }
    red[slice][d] = acc;
    __syncthreads();
    if (t < 32) {
        float s = 0.f;
#pragma unroll
        for (int sl = 0; sl < 8; sl++) s += red[sl][t];
        g_p[b * EMB + h * DD + t] = s + 1024.f * bm[h * DD + t];
    }
}

// ---------------- K6: final MLP head ----------------
__global__ __launch_bounds__(256) void k6_mlp(
    const float* __restrict__ Wp, const float* __restrict__ bp,
    const float* __restrict__ gamma, const float* __restrict__ beta,
    const float* __restrict__ rmean, const float* __restrict__ rvar,
    const float* __restrict__ W1, const float* __restrict__ b1,
    const float* __restrict__ W2, const float* __restrict__ b2,
    float* __restrict__ out)
{
    __shared__ float p_s[256];
    __shared__ float y_s[512];
    __shared__ float z_s[256];
    __shared__ float w_s[128];
    int b = blockIdx.x, t = threadIdx.x;

    p_s[t] = g_p[b * EMB + t];
    __syncthreads();
#pragma unroll
    for (int r = 0; r < 2; r++) {
        int o = r * 256 + t;
        float acc = bp[o];
#pragma unroll 4
        for (int k = 0; k < 256; k++) acc += p_s[k] * Wp[k * 512 + o];
        acc = (acc - rmean[o]) * rsqrtf(rvar[o] + 1e-5f) * gamma[o] + beta[o];
        y_s[o] = fmaxf(acc, 0.f);
    }
    __syncthreads();
    {
        float acc = b1[t];
#pragma unroll 4
        for (int k = 0; k < 512; k++) acc += y_s[k] * W1[k * 256 + t];
        z_s[t] = fmaxf(acc, 0.f);
    }
    __syncthreads();
    if (t < 128) {
        float acc = b2[t];
#pragma unroll 4
        for (int k = 0; k < 256; k++) acc += z_s[k] * W2[k * 128 + t];
        w_s[t] = fmaxf(acc, 0.f);
    }
    __syncthreads();
    if (t < 64) w_s[t] += w_s[t + 64];
    __syncthreads();
    if (t < 32) {
        float v = w_s[t] + w_s[t + 32];
#pragma unroll
        for (int off = 16; off; off >>= 1) v += __shfl_xor_sync(0xffffffffu, v, off);
        if (t == 0) out[b] = v * (1.f / 128.f);
    }
}

// ---------------- launch ----------------
extern "C" void kernel_launch(void* const* d_in, const int* in_sizes, int n_in,
                              void* d_out, int out_size)
{
    const float* x     = (const float*)d_in[0];
    const float* adj   = (const float*)d_in[1];
    const float* Ws    = (const float*)d_in[2];
    const float* bs    = (const float*)d_in[3];
    const float* qs    = (const float*)d_in[4];
    const float* qbs   = (const float*)d_in[5];
    const float* Wm    = (const float*)d_in[6];
    const float* bm    = (const float*)d_in[7];
    const float* qm    = (const float*)d_in[8];
    const float* qbm   = (const float*)d_in[9];
    const float* Wp    = (const float*)d_in[10];
    const float* bp    = (const float*)d_in[11];
    const float* gamma = (const float*)d_in[12];
    const float* beta  = (const float*)d_in[13];
    const float* rmean = (const float*)d_in[14];
    const float* rvar  = (const float*)d_in[15];
    const float* W1    = (const float*)d_in[16];
    const float* b1    = (const float*)d_in[17];
    const float* W2    = (const float*)d_in[18];
    const float* b2    = (const float*)d_in[19];
    float* out = (float*)d_out;

    k1_wh1<<<(BB * HH * NN) / 256, 256>>>(x, Ws, bs, qs, qbs);
    k3v<<<1, 256>>>(Wm, bm, qm, qbm);
    k2_mma<<<dim3(NN / 64, BB), 256>>>(adj);
    k4_zrow<<<dim3(NN / 8, BB), 256>>>(adj);
    k5a_colsum<<<dim3(4, 4, BB), 256>>>(adj);
    k5b_pool<<<dim3(HH, BB), 256>>>(Wm, bm);
    k6_mlp<<<BB, 256>>>(Wp, bp, gamma, beta, rmean, rvar, W1, b1, W2, b2, out);
}

// round 5
// speedup vs baseline: 2.0665x; 1.1896x over previous
#include <cuda_runtime.h>
#include <cuda_fp16.h>
#include <cstdint>
#include <cstddef>

// Shapes
#define BB   16
#define NN   1024
#define FIN  7
#define HH   8
#define DD   32
#define EMB  256
#define LOG2E 1.4426950408889634f

// ---------------- scratch ----------------
__device__ __half g_WhTh[BB * HH * DD * NN];  // [b][h][d][n] half, 8 MB
__device__ float g_c1 [BB * HH * NN];
__device__ float g_h1 [BB * NN * EMB];        // [b][n][h*32+d] 16 MB
__device__ float g_c2 [BB * HH * NN];         // k2 atomically accumulates h1.v
__device__ float g_zi [BB * HH * NN];         // SCALED: ziS = 1024/Z
__device__ float g_g  [BB * HH * NN];
__device__ float g_v  [HH * EMB];
__device__ float g_cb [HH];
__device__ float g_p  [BB * EMB];
__device__ float4 g_R4[BB * NN];              // row power sums R1..R4
__device__ float g_R5 [BB * NN];              // R5
__device__ float g_s0 [BB * HH];              // sum_i ziS per (b,h)

// ---------------- half2 helpers (uint32-carried) ----------------
__device__ __forceinline__ uint32_t h2exp2_u(uint32_t x) {
    uint32_t r; asm("ex2.approx.f16x2 %0, %1;" : "=r"(r) : "r"(x)); return r;
}
__device__ __forceinline__ uint32_t h2mul_u(uint32_t a, uint32_t b) {
    uint32_t r; asm("mul.f16x2 %0, %1, %2;" : "=r"(r) : "r"(a), "r"(b)); return r;
}
__device__ __forceinline__ uint32_t h2add_u(uint32_t a, uint32_t b) {
    uint32_t r; asm("add.f16x2 %0, %1, %2;" : "=r"(r) : "r"(a), "r"(b)); return r;
}
__device__ __forceinline__ uint32_t h2fma_u(uint32_t a, uint32_t b, uint32_t c) {
    uint32_t r; asm("fma.rn.f16x2 %0, %1, %2, %3;" : "=r"(r) : "r"(a), "r"(b), "r"(c)); return r;
}
// pack {lo, hi} floats -> half2 (hi in upper half)
__device__ __forceinline__ uint32_t f22h2_u(float hi, float lo) {
    uint32_t r; asm("cvt.rn.f16x2.f32 %0, %1, %2;" : "=r"(r) : "f"(hi), "f"(lo)); return r;
}
__device__ __forceinline__ float2 h22f2(uint32_t h) {
    float2 f;
    asm("{ .reg .f16 l, hh; mov.b32 {l, hh}, %2; cvt.f32.f16 %0, l; cvt.f32.f16 %1, hh; }"
        : "=f"(f.x), "=f"(f.y) : "r"(h));
    return f;
}

#define CP_ASYNC16(dst, src) \
    asm volatile("cp.async.cg.shared.global [%0], [%1], 16;" :: "r"(dst), "l"(src) : "memory")
#define CP_COMMIT() asm volatile("cp.async.commit_group;" ::: "memory")
#define CP_WAIT(n)  asm volatile("cp.async.wait_group %0;" :: "n"(n) : "memory")

#define MMA_F16(c, a0, a1, a2, a3, b0, b1) \
    asm volatile("mma.sync.aligned.m16n8k16.row.col.f32.f16.f16.f32 " \
        "{%0,%1,%2,%3}, {%4,%5,%6,%7}, {%8,%9}, {%0,%1,%2,%3};" \
        : "+f"((c)[0]), "+f"((c)[1]), "+f"((c)[2]), "+f"((c)[3]) \
        : "r"(a0), "r"(a1), "r"(a2), "r"(a3), "r"(b0), "r"(b1))

__device__ __forceinline__ uint32_t smem_u32(const void* p) {
    uint32_t a;
    asm("{ .reg .u64 t; cvta.to.shared.u64 t, %1; cvt.u32.u64 %0, t; }" : "=r"(a) : "l"(p));
    return a;
}

// ---------------- K1: WhTh = half((x@Ws + bs)^T); c1; zero c2 ----------------
__global__ __launch_bounds__(256) void k1_wh1(
    const float* __restrict__ x,  const float* __restrict__ Ws,
    const float* __restrict__ bs, const float* __restrict__ qs,
    const float* __restrict__ qbs)
{
    int idx = blockIdx.x * blockDim.x + threadIdx.x;
    int n = idx & (NN - 1);
    int h = (idx >> 10) & (HH - 1);
    int b = idx >> 13;

    g_c2[idx] = 0.f;

    float xv[FIN];
    const float* xr = x + ((size_t)(b * NN + n)) * FIN;
#pragma unroll
    for (int i = 0; i < FIN; i++) xv[i] = xr[i];

    const float* W = Ws + h * FIN * DD;
    float s = qbs[h];
    __half* outT = g_WhTh + ((size_t)(b * HH + h) * DD) * NN + n;
#pragma unroll
    for (int d = 0; d < DD; d++) {
        float acc = bs[h * DD + d];
#pragma unroll
        for (int i = 0; i < FIN; i++) acc += xv[i] * W[i * DD + d];
        outT[(size_t)d * NN] = __float2half_rn(acc);
        s += acc * (qs[h * 2 * DD + d] + qs[h * 2 * DD + DD + d]);
    }
    g_c1[idx] = s > 0.f ? s : 0.01f * s;
}

// ---------------- K3v: v[h][k], cb[h] ----------------
__global__ __launch_bounds__(256) void k3v(
    const float* __restrict__ Wm, const float* __restrict__ bm,
    const float* __restrict__ qm, const float* __restrict__ qbm)
{
    int t = threadIdx.x;
#pragma unroll
    for (int p = 0; p < 8; p++) {
        int idx = p * 256 + t;
        int h = idx >> 8, k = idx & 255;
        float s = 0.f;
#pragma unroll
        for (int d = 0; d < DD; d++)
            s += Wm[(h * EMB + k) * DD + d] * (qm[h * 2 * DD + d] + qm[h * 2 * DD + DD + d]);
        g_v[idx] = s;
    }
    if (t < HH) {
        float s = 0.f;
#pragma unroll
        for (int d = 0; d < DD; d++)
            s += bm[t * DD + d] * (qm[t * 2 * DD + d] + qm[t * 2 * DD + DD + d]);
        g_cb[t] = s + qbm[t];
    }
}

// ---------------- kR: row power sums R1..R5 of adj; zero g_g, g_s0 ----------------
// grid (128, 16), 256 thr, warp per row.
__global__ __launch_bounds__(256) void kR_pow(const float* __restrict__ adj)
{
    int b = blockIdx.y;
    int t = threadIdx.x;
    if (t < 64) g_g[b * (HH * NN) + blockIdx.x * 64 + t] = 0.f;
    if (blockIdx.x == 0 && b == 0 && t < BB * HH) g_s0[t] = 0.f;

    int w = t >> 5, lane = t & 31;
    int i = blockIdx.x * 8 + w;
    const float4* row = (const float4*)(adj + ((size_t)(b * NN + i)) * NN);

    float4 va[8];
#pragma unroll
    for (int q = 0; q < 8; q++) va[q] = row[q * 32 + lane];

    float r1 = 0.f, r2 = 0.f, r3 = 0.f, r4 = 0.f, r5 = 0.f;
#pragma unroll
    for (int q = 0; q < 8; q++) {
        float vv[4] = {va[q].x, va[q].y, va[q].z, va[q].w};
#pragma unroll
        for (int e = 0; e < 4; e++) {
            float a = vv[e], a2 = a * a, a3 = a2 * a;
            r1 += a; r2 += a2; r3 += a3; r4 += a2 * a2; r5 += a2 * a3;
        }
    }
#pragma unroll
    for (int off = 16; off; off >>= 1) {
        r1 += __shfl_xor_sync(0xffffffffu, r1, off);
        r2 += __shfl_xor_sync(0xffffffffu, r2, off);
        r3 += __shfl_xor_sync(0xffffffffu, r3, off);
        r4 += __shfl_xor_sync(0xffffffffu, r4, off);
        r5 += __shfl_xor_sync(0xffffffffu, r5, off);
    }
    if (lane == 0) {
        g_R4[b * NN + i] = make_float4(r1, r2, r3, r4);
        g_R5[b * NN + i] = r5;
    }
}

// ---------------- K2: layer-1 attention via mma.sync f16 m16n8k16 ----------------
__global__ __launch_bounds__(256, 2) void k2_mma(const float* __restrict__ adj)
{
    __shared__ float adj_s[2][64 * 72];
    __shared__ float v_s[HH * EMB];

    int t = threadIdx.x;
    int lane = t & 31, h = t >> 5;
    int gid = lane >> 2, tig = lane & 3;
    int i0 = blockIdx.x * 64, b = blockIdx.y;

#pragma unroll
    for (int p = 0; p < 8; p++) v_s[p * 256 + t] = g_v[p * 256 + t];

    const float* adjb = adj + (size_t)b * NN * NN;
    const __half* whT = g_WhTh + (size_t)((b * HH + h) * DD) * NN;
    const float* c1p  = g_c1 + (b * HH + h) * NN + i0;

    uint32_t clb[4][2];
#pragma unroll
    for (int mt = 0; mt < 4; mt++) {
        float c0 = c1p[mt * 16 + gid]     * LOG2E;
        float c1 = c1p[mt * 16 + gid + 8] * LOG2E;
        clb[mt][0] = f22h2_u(c0, c0);
        clb[mt][1] = f22h2_u(c1, c1);
    }

    float acc[4][4][4];
    uint32_t z2a[4], z2b[4];
    float zf0[4], zf1[4];
#pragma unroll
    for (int mt = 0; mt < 4; mt++) {
        z2a[mt] = 0u; z2b[mt] = 0u; zf0[mt] = 0.f; zf1[mt] = 0.f;
#pragma unroll
        for (int nt = 0; nt < 4; nt++)
#pragma unroll
            for (int r = 0; r < 4; r++) acc[mt][nt][r] = 0.f;
    }

    uint32_t sbase = smem_u32(adj_s);

#define PREFETCH(tile, buf) do { \
        uint32_t dst0 = sbase + (buf) * (64 * 72 * 4); \
        const float* srcb = adjb + (size_t)i0 * NN + (tile) * 64; \
        _Pragma("unroll") \
        for (int p = 0; p < 4; p++) { \
            int idx = p * 256 + t; \
            int row = idx >> 4, f4 = idx & 15; \
            CP_ASYNC16(dst0 + (row * 72 + f4 * 4) * 4, \
                       srcb + (size_t)row * NN + f4 * 4); \
        } \
        CP_COMMIT(); \
    } while (0)

    PREFETCH(0, 0);

#pragma unroll 1
    for (int tile = 0; tile < 16; tile++) {
        if (tile + 1 < 16) { PREFETCH(tile + 1, (tile + 1) & 1); CP_WAIT(1); }
        else               { CP_WAIT(0); }
        __syncthreads();
        const float* As = adj_s[tile & 1];

#pragma unroll
        for (int ks = 0; ks < 4; ks++) {
            int kg = tile * 64 + ks * 16;
            uint32_t b0[4], b1[4];
            const __half* Bp = whT + (size_t)gid * NN + kg + 2 * tig;
#pragma unroll
            for (int nt = 0; nt < 4; nt++) {
                b0[nt] = *(const uint32_t*)(Bp + (size_t)nt * 8 * NN);
                b1[nt] = *(const uint32_t*)(Bp + (size_t)nt * 8 * NN + 8);
            }
#pragma unroll
            for (int mt = 0; mt < 4; mt++) {
                int rb = mt * 16 + gid;
                const float* base = As + ks * 16 + 2 * tig;
                float2 rl0 = *(const float2*)(base + rb * 72);
                float2 rl1 = *(const float2*)(base + (rb + 8) * 72);
                float2 rh0 = *(const float2*)(base + rb * 72 + 8);
                float2 rh1 = *(const float2*)(base + (rb + 8) * 72 + 8);
                uint32_t a0 = h2exp2_u(h2mul_u(clb[mt][0], f22h2_u(rl0.y, rl0.x)));
                uint32_t a1 = h2exp2_u(h2mul_u(clb[mt][1], f22h2_u(rl1.y, rl1.x)));
                uint32_t a2 = h2exp2_u(h2mul_u(clb[mt][0], f22h2_u(rh0.y, rh0.x)));
                uint32_t a3 = h2exp2_u(h2mul_u(clb[mt][1], f22h2_u(rh1.y, rh1.x)));
                z2a[mt] = h2add_u(z2a[mt], h2add_u(a0, a2));
                z2b[mt] = h2add_u(z2b[mt], h2add_u(a1, a3));
#pragma unroll
                for (int nt = 0; nt < 4; nt++)
                    MMA_F16(acc[mt][nt], a0, a1, a2, a3, b0[nt], b1[nt]);
            }
        }
        // flush Z partials to f32 once per tile
#pragma unroll
        for (int mt = 0; mt < 4; mt++) {
            float2 fa = h22f2(z2a[mt]); zf0[mt] += fa.x + fa.y; z2a[mt] = 0u;
            float2 fb = h22f2(z2b[mt]); zf1[mt] += fb.x + fb.y; z2b[mt] = 0u;
        }
        __syncthreads();
    }

    // Z: reduce over tig (lanes xor 1, 2)
#pragma unroll
    for (int mt = 0; mt < 4; mt++) {
        zf0[mt] += __shfl_xor_sync(0xffffffffu, zf0[mt], 1);
        zf0[mt] += __shfl_xor_sync(0xffffffffu, zf0[mt], 2);
        zf1[mt] += __shfl_xor_sync(0xffffffffu, zf1[mt], 1);
        zf1[mt] += __shfl_xor_sync(0xffffffffu, zf1[mt], 2);
    }

#pragma unroll
    for (int mt = 0; mt < 4; mt++) {
        float zi0 = 1.f / zf0[mt], zi1 = 1.f / zf1[mt];

        int r0 = i0 + mt * 16 + gid;
        float* o0 = g_h1 + ((size_t)(b * NN + r0)) * EMB + h * 32;
        float* o1 = o0 + (size_t)8 * EMB;
        float q0[4][2], q1[4][2];
#pragma unroll
        for (int nt = 0; nt < 4; nt++) {
            q0[nt][0] = acc[mt][nt][0] * zi0; q0[nt][1] = acc[mt][nt][1] * zi0;
            q1[nt][0] = acc[mt][nt][2] * zi1; q1[nt][1] = acc[mt][nt][3] * zi1;
            *(float2*)(o0 + nt * 8 + 2 * tig) = make_float2(q0[nt][0], q0[nt][1]);
            *(float2*)(o1 + nt * 8 + 2 * tig) = make_float2(q1[nt][0], q1[nt][1]);
        }
#pragma unroll
        for (int th = 0; th < HH; th++) {
            float p0 = 0.f, p1 = 0.f;
#pragma unroll
            for (int nt = 0; nt < 4; nt++) {
                float2 vv = *(const float2*)&v_s[th * 256 + h * 32 + nt * 8 + 2 * tig];
                p0 += q0[nt][0] * vv.x + q0[nt][1] * vv.y;
                p1 += q1[nt][0] * vv.x + q1[nt][1] * vv.y;
            }
            p0 += __shfl_xor_sync(0xffffffffu, p0, 1);
            p0 += __shfl_xor_sync(0xffffffffu, p0, 2);
            p1 += __shfl_xor_sync(0xffffffffu, p1, 1);
            p1 += __shfl_xor_sync(0xffffffffu, p1, 2);
            if (tig == 0) {
                atomicAdd(&g_c2[(b * HH + th) * NN + r0], p0);
                atomicAdd(&g_c2[(b * HH + th) * NN + r0 + 8], p1);
            }
        }
    }
#undef PREFETCH
}

// ---------------- K4: finalize c2; Z via Taylor from R_m; ziS; S0 ----------------
// grid 512, 256 thr. One (b,h) per block (256 consecutive n).
__global__ __launch_bounds__(256) void k4_z()
{
    int idx = blockIdx.x * 256 + threadIdx.x;
    int n = idx & (NN - 1);
    int h = (idx >> 10) & (HH - 1);
    int b = idx >> 13;

    float raw = g_c2[idx] + g_cb[h];
    float c = raw > 0.f ? raw : 0.01f * raw;
    g_c2[idx] = c;

    float4 R = g_R4[b * NN + n];
    float R5 = g_R5[b * NN + n];
    float Z = 1024.f + c * (R.x + c * (0.5f * R.y + c * ((1.f / 6.f) * R.z
                + c * ((1.f / 24.f) * R.w + c * ((1.f / 120.f) * R5)))));
    float ziS = 1024.f / Z;
    g_zi[idx] = ziS;

    // reduce ziS across warp, one atomic per warp
    float s = ziS;
#pragma unroll
    for (int off = 16; off; off >>= 1) s += __shfl_xor_sync(0xffffffffu, s, off);
    if ((threadIdx.x & 31) == 0) atomicAdd(&g_s0[b * HH + h], s);
}

// ---------------- K5a: g[j] += sum_i ziS_i * (exp(c_i a_ij) - 1) via Taylor ----------------
// grid (4 jblk, 4 iblk, 16 b), 256 thr. Thread: 4 j's (float4), 64 i's.
__global__ __launch_bounds__(256) void k5a_colsum(const float* __restrict__ adj)
{
    __shared__ uint4 w4s[4][256];   // [headpair][i] -> (w1,w2,w3,w4) half2 packs, 16 KB
    int b = blockIdx.z, j0 = blockIdx.x * 256, i0 = blockIdx.y * 256;
    int t = threadIdx.x;
    {
        int i = i0 + t;
#pragma unroll
        for (int p = 0; p < 4; p++) {
            float c0 = g_c2[(b * HH + 2 * p)     * NN + i];
            float c1 = g_c2[(b * HH + 2 * p + 1) * NN + i];
            float z0 = g_zi[(b * HH + 2 * p)     * NN + i];
            float z1 = g_zi[(b * HH + 2 * p + 1) * NN + i];
            float w1a = z0 * c0,               w1b = z1 * c1;
            float w2a = w1a * c0 * 0.5f,       w2b = w1b * c1 * 0.5f;
            float w3a = w2a * c0 * (1.f/3.f),  w3b = w2b * c1 * (1.f/3.f);
            float w4a = w3a * c0 * 0.25f,      w4b = w3b * c1 * 0.25f;
            w4s[p][t] = make_uint4(f22h2_u(w1b, w1a), f22h2_u(w2b, w2a),
                                   f22h2_u(w3b, w3a), f22h2_u(w4b, w4a));
        }
    }
    __syncthreads();

    int jq = t & 63, iq = t >> 6;
    const float4* colp = (const float4*)(adj + (size_t)b * NN * NN)
                       + (size_t)(i0 + iq * 64) * (NN / 4) + (j0 >> 2) + jq;

    float gf[4][8];
#pragma unroll
    for (int jj = 0; jj < 4; jj++)
#pragma unroll
        for (int hh = 0; hh < 8; hh++) gf[jj][hh] = 0.f;

#pragma unroll 1
    for (int ib = 0; ib < 4; ib++) {
        uint32_t ac[4][4];
#pragma unroll
        for (int jj = 0; jj < 4; jj++)
#pragma unroll
            for (int p = 0; p < 4; p++) ac[jj][p] = 0u;

#pragma unroll
        for (int ii = 0; ii < 16; ii++) {
            int i = ib * 16 + ii;
            float4 v = colp[(size_t)i * (NN / 4)];
            uint4 wv[4];
#pragma unroll
            for (int p = 0; p < 4; p++) wv[p] = w4s[p][iq * 64 + i];
            float vvx[4] = {v.x, v.y, v.z, v.w};
#pragma unroll
            for (int jj = 0; jj < 4; jj++) {
                uint32_t ah = f22h2_u(vvx[jj], vvx[jj]);
#pragma unroll
                for (int p = 0; p < 4; p++) {
                    uint32_t q = h2fma_u(wv[p].w, ah, wv[p].z);
                    q = h2fma_u(q, ah, wv[p].y);
                    q = h2fma_u(q, ah, wv[p].x);
                    q = h2mul_u(q, ah);
                    ac[jj][p] = h2add_u(ac[jj][p], q);
                }
            }
        }
#pragma unroll
        for (int jj = 0; jj < 4; jj++)
#pragma unroll
            for (int p = 0; p < 4; p++) {
                float2 f = h22f2(ac[jj][p]);
                gf[jj][2 * p] += f.x; gf[jj][2 * p + 1] += f.y;
            }
    }
#pragma unroll
    for (int jj = 0; jj < 4; jj++)
#pragma unroll
        for (int hh = 0; hh < 8; hh++)
            atomicAdd(&g_g[(b * HH + hh) * NN + j0 + jq * 4 + jj], gf[jj][hh]);
}

// ---------------- K5b: u = sum_j g_j * h1_j ; p = u@Wm + 1024*bm ----------------
__global__ __launch_bounds__(256) void k5b_pool(
    const float* __restrict__ Wm, const float* __restrict__ bm)
{
    __shared__ float g_sm[NN];
    __shared__ float u_s[EMB];
    __shared__ float red[8][32];
    int b = blockIdx.y, h = blockIdx.x;
    int t = threadIdx.x;

    float s0 = g_s0[b * HH + h];
#pragma unroll
    for (int p = 0; p < 4; p++)
        g_sm[p * 256 + t] = (g_g[(b * HH + h) * NN + p * 256 + t] + s0) * (1.f / 1024.f);
    __syncthreads();

    float u = 0.f;
    const float* h1p = g_h1 + (size_t)b * NN * EMB + t;
#pragma unroll 4
    for (int j = 0; j < NN; j++)
        u += g_sm[j] * h1p[(size_t)j * EMB];
    u_s[t] = u;
    __syncthreads();

    int d = t & 31, slice = t >> 5;
    const float* wm = Wm + h * EMB * DD;
    float acc = 0.f;
#pragma unroll
    for (int kk = 0; kk < 32; kk++) {
        int k = slice * 32 + kk;
        acc += u_s[k] * wm[k * DD + d];
    }
    red[slice][d] = acc;
    __syncthreads();
    if (t < 32) {
        float s = 0.f;
#pragma unroll
        for (int sl = 0; sl < 8; sl++) s += red[sl][t];
        g_p[b * EMB + h * DD + t] = s + 1024.f * bm[h * DD + t];
    }
}

// ---------------- K6: final MLP head ----------------
__global__ __launch_bounds__(256) void k6_mlp(
    const float* __restrict__ Wp, const float* __restrict__ bp,
    const float* __restrict__ gamma, const float* __restrict__ beta,
    const float* __restrict__ rmean, const float* __restrict__ rvar,
    const float* __restrict__ W1, const float* __restrict__ b1,
    const float* __restrict__ W2, const float* __restrict__ b2,
    float* __restrict__ out)
{
    __shared__ float p_s[256];
    __shared__ float y_s[512];
    __shared__ float z_s[256];
    __shared__ float w_s[128];
    int b = blockIdx.x, t = threadIdx.x;

    p_s[t] = g_p[b * EMB + t];
    __syncthreads();
#pragma unroll
    for (int r = 0; r < 2; r++) {
        int o = r * 256 + t;
        float acc = bp[o];
#pragma unroll 4
        for (int k = 0; k < 256; k++) acc += p_s[k] * Wp[k * 512 + o];
        acc = (acc - rmean[o]) * rsqrtf(rvar[o] + 1e-5f) * gamma[o] + beta[o];
        y_s[o] = fmaxf(acc, 0.f);
    }
    __syncthreads();
    {
        float acc = b1[t];
#pragma unroll 4
        for (int k = 0; k < 512; k++) acc += y_s[k] * W1[k * 256 + t];
        z_s[t] = fmaxf(acc, 0.f);
    }
    __syncthreads();
    if (t < 128) {
        float acc = b2[t];
#pragma unroll 4
        for (int k = 0; k < 256; k++) acc += z_s[k] * W2[k * 128 + t];
        w_s[t] = fmaxf(acc, 0.f);
    }
    __syncthreads();
    if (t < 64) w_s[t] += w_s[t + 64];
    __syncthreads();
    if (t < 32) {
        float v = w_s[t] + w_s[t + 32];
#pragma unroll
        for (int off = 16; off; off >>= 1) v += __shfl_xor_sync(0xffffffffu, v, off);
        if (t == 0) out[b] = v * (1.f / 128.f);
    }
}

// ---------------- launch ----------------
extern "C" void kernel_launch(void* const* d_in, const int* in_sizes, int n_in,
                              void* d_out, int out_size)
{
    const float* x     = (const float*)d_in[0];
    const float* adj   = (const float*)d_in[1];
    const float* Ws    = (const float*)d_in[2];
    const float* bs    = (const float*)d_in[3];
    const float* qs    = (const float*)d_in[4];
    const float* qbs   = (const float*)d_in[5];
    const float* Wm    = (const float*)d_in[6];
    const float* bm    = (const float*)d_in[7];
    const float* qm    = (const float*)d_in[8];
    const float* qbm   = (const float*)d_in[9];
    const float* Wp    = (const float*)d_in[10];
    const float* bp    = (const float*)d_in[11];
    const float* gamma = (const float*)d_in[12];
    const float* beta  = (const float*)d_in[13];
    const float* rmean = (const float*)d_in[14];
    const float* rvar  = (const float*)d_in[15];
    const float* W1    = (const float*)d_in[16];
    const float* b1    = (const float*)d_in[17];
    const float* W2    = (const float*)d_in[18];
    const float* b2    = (const float*)d_in[19];
    float* out = (float*)d_out;

    k1_wh1<<<(BB * HH * NN) / 256, 256>>>(x, Ws, bs, qs, qbs);
    k3v<<<1, 256>>>(Wm, bm, qm, qbm);
    kR_pow<<<dim3(NN / 8, BB), 256>>>(adj);
    k2_mma<<<dim3(NN / 64, BB), 256>>>(adj);          // 4th launch -> ncu target
    k4_z<<<(BB * HH * NN) / 256, 256>>>();
    k5a_colsum<<<dim3(4, 4, BB), 256>>>(adj);
    k5b_pool<<<dim3(HH, BB), 256>>>(Wm, bm);
    k6_mlp<<<BB, 256>>>(Wp, bp, gamma, beta, rmean, rvar, W1, b1, W2, b2, out);
}

// round 6
// speedup vs baseline: 2.3698x; 1.1467x over previous
#include <cuda_runtime.h>
#include <cuda_fp16.h>
#include <cstdint>
#include <cstddef>

// Shapes
#define BB   16
#define NN   1024
#define FIN  7
#define HH   8
#define DD   32
#define EMB  256
#define LOG2E 1.4426950408889634f

// ---------------- scratch ----------------
__device__ __half g_adjh[BB * NN * NN];       // half copy of adj, 32 MB
__device__ __half g_WhTh[BB * HH * DD * NN];  // [b][h][d][n] half, 8 MB
__device__ float g_c1 [BB * HH * NN];
__device__ float g_h1 [BB * NN * EMB];        // [b][n][h*32+d] 16 MB
__device__ float g_c2 [BB * HH * NN];
__device__ float g_zi [BB * HH * NN];         // ziS = 1024/Z
__device__ float g_g  [BB * HH * NN];
__device__ float g_v  [HH * EMB];
__device__ float g_cb [HH];
__device__ float g_p  [BB * EMB];
__device__ float4 g_R4[BB * NN];              // row power sums R1..R4
__device__ float g_R5 [BB * NN];              // R5
__device__ float g_s0 [BB * HH];

// ---------------- half2 helpers ----------------
__device__ __forceinline__ uint32_t h2exp2_u(uint32_t x) {
    uint32_t r; asm("ex2.approx.f16x2 %0, %1;" : "=r"(r) : "r"(x)); return r;
}
__device__ __forceinline__ uint32_t h2mul_u(uint32_t a, uint32_t b) {
    uint32_t r; asm("mul.f16x2 %0, %1, %2;" : "=r"(r) : "r"(a), "r"(b)); return r;
}
__device__ __forceinline__ uint32_t h2add_u(uint32_t a, uint32_t b) {
    uint32_t r; asm("add.f16x2 %0, %1, %2;" : "=r"(r) : "r"(a), "r"(b)); return r;
}
__device__ __forceinline__ uint32_t h2fma_u(uint32_t a, uint32_t b, uint32_t c) {
    uint32_t r; asm("fma.rn.f16x2 %0, %1, %2, %3;" : "=r"(r) : "r"(a), "r"(b), "r"(c)); return r;
}
__device__ __forceinline__ uint32_t f22h2_u(float hi, float lo) {
    uint32_t r; asm("cvt.rn.f16x2.f32 %0, %1, %2;" : "=r"(r) : "f"(hi), "f"(lo)); return r;
}
__device__ __forceinline__ uint32_t f2h2b(float a) {
    uint32_t r;
    asm("{ .reg .f16 v; cvt.rn.f16.f32 v, %1; mov.b32 %0, {v, v}; }" : "=r"(r) : "f"(a));
    return r;
}
__device__ __forceinline__ float2 h22f2(uint32_t h) {
    float2 f;
    asm("{ .reg .f16 l, hh; mov.b32 {l, hh}, %2; cvt.f32.f16 %0, l; cvt.f32.f16 %1, hh; }"
        : "=f"(f.x), "=f"(f.y) : "r"(h));
    return f;
}

#define CP_ASYNC16(dst, src) \
    asm volatile("cp.async.cg.shared.global [%0], [%1], 16;" :: "r"(dst), "l"(src) : "memory")
#define CP_COMMIT() asm volatile("cp.async.commit_group;" ::: "memory")
#define CP_WAIT(n)  asm volatile("cp.async.wait_group %0;" :: "n"(n) : "memory")

#define MMA_F16(c, a0, a1, a2, a3, b0, b1) \
    asm volatile("mma.sync.aligned.m16n8k16.row.col.f32.f16.f16.f32 " \
        "{%0,%1,%2,%3}, {%4,%5,%6,%7}, {%8,%9}, {%0,%1,%2,%3};" \
        : "+f"((c)[0]), "+f"((c)[1]), "+f"((c)[2]), "+f"((c)[3]) \
        : "r"(a0), "r"(a1), "r"(a2), "r"(a3), "r"(b0), "r"(b1))

__device__ __forceinline__ uint32_t smem_u32(const void* p) {
    uint32_t a;
    asm("{ .reg .u64 t; cvta.to.shared.u64 t, %1; cvt.u32.u64 %0, t; }" : "=r"(a) : "l"(p));
    return a;
}

// ---------------- K1: WhTh = half((x@Ws + bs)^T); c1; zero c2 ----------------
__global__ __launch_bounds__(256) void k1_wh1(
    const float* __restrict__ x,  const float* __restrict__ Ws,
    const float* __restrict__ bs, const float* __restrict__ qs,
    const float* __restrict__ qbs)
{
    int idx = blockIdx.x * blockDim.x + threadIdx.x;
    int n = idx & (NN - 1);
    int h = (idx >> 10) & (HH - 1);
    int b = idx >> 13;

    g_c2[idx] = 0.f;

    float xv[FIN];
    const float* xr = x + ((size_t)(b * NN + n)) * FIN;
#pragma unroll
    for (int i = 0; i < FIN; i++) xv[i] = xr[i];

    const float* W = Ws + h * FIN * DD;
    float s = qbs[h];
    __half* outT = g_WhTh + ((size_t)(b * HH + h) * DD) * NN + n;
#pragma unroll
    for (int d = 0; d < DD; d++) {
        float acc = bs[h * DD + d];
#pragma unroll
        for (int i = 0; i < FIN; i++) acc += xv[i] * W[i * DD + d];
        outT[(size_t)d * NN] = __float2half_rn(acc);
        s += acc * (qs[h * 2 * DD + d] + qs[h * 2 * DD + DD + d]);
    }
    g_c1[idx] = s > 0.f ? s : 0.01f * s;
}

// ---------------- K3v: v[h][k] (warp per (h,k), coalesced); cb[h] ----------------
__global__ __launch_bounds__(256) void k3v(
    const float* __restrict__ Wm, const float* __restrict__ bm,
    const float* __restrict__ qm, const float* __restrict__ qbm)
{
    int wg = blockIdx.x * 8 + (threadIdx.x >> 5);   // 0..2047 = (h,k)
    int lane = threadIdx.x & 31;
    int h = wg >> 8, k = wg & 255;

    float q = qm[h * 64 + lane] + qm[h * 64 + 32 + lane];
    float s = Wm[((size_t)(h * EMB + k)) * DD + lane] * q;
#pragma unroll
    for (int off = 16; off; off >>= 1) s += __shfl_xor_sync(0xffffffffu, s, off);
    if (lane == 0) g_v[h * EMB + k] = s;

    if (blockIdx.x == 0) {
        int w = threadIdx.x >> 5;   // handle h = w
        float q2 = qm[w * 64 + lane] + qm[w * 64 + 32 + lane];
        float s2 = bm[w * DD + lane] * q2;
#pragma unroll
        for (int off = 16; off; off >>= 1) s2 += __shfl_xor_sync(0xffffffffu, s2, off);
        if (lane == 0) g_cb[w] = s2 + qbm[w];
    }
}

// ---------------- kC: adj -> half; row power sums R1..R5; zero g_g, g_s0 ----------------
// grid (128, 16), 256 thr, warp per row.
__global__ __launch_bounds__(256) void kC_conv(const float* __restrict__ adj)
{
    int b = blockIdx.y;
    int t = threadIdx.x;
    if (t < 64) g_g[b * (HH * NN) + blockIdx.x * 64 + t] = 0.f;
    if (blockIdx.x == 0 && b == 0 && t < BB * HH) g_s0[t] = 0.f;

    int w = t >> 5, lane = t & 31;
    int i = blockIdx.x * 8 + w;
    const float4* row = (const float4*)(adj + ((size_t)(b * NN + i)) * NN);
    __half* hrow = g_adjh + ((size_t)(b * NN + i)) * NN;

    float r1 = 0.f, r2 = 0.f, r3 = 0.f, r4 = 0.f, r5 = 0.f;
#pragma unroll
    for (int q = 0; q < 8; q++) {
        float4 va = row[q * 32 + lane];
        uint2 pk = make_uint2(f22h2_u(va.y, va.x), f22h2_u(va.w, va.z));
        *(uint2*)(hrow + 4 * (q * 32 + lane)) = pk;
        float vv[4] = {va.x, va.y, va.z, va.w};
#pragma unroll
        for (int e = 0; e < 4; e++) {
            float a = vv[e], a2 = a * a, a3 = a2 * a;
            r1 += a; r2 += a2; r3 += a3; r4 += a2 * a2; r5 += a2 * a3;
        }
    }
#pragma unroll
    for (int off = 16; off; off >>= 1) {
        r1 += __shfl_xor_sync(0xffffffffu, r1, off);
        r2 += __shfl_xor_sync(0xffffffffu, r2, off);
        r3 += __shfl_xor_sync(0xffffffffu, r3, off);
        r4 += __shfl_xor_sync(0xffffffffu, r4, off);
        r5 += __shfl_xor_sync(0xffffffffu, r5, off);
    }
    if (lane == 0) {
        g_R4[b * NN + i] = make_float4(r1, r2, r3, r4);
        g_R5[b * NN + i] = r5;
    }
}

// ---------------- K2: layer-1 attention, half adj tiles, mma.sync f16 ----------------
// CTA = (64-row i-block, b), 256 thr, warp = head.
// Smem tile: 64 rows x 64 half, padded row stride 36 words (144 B) -> conflict-free.
__global__ __launch_bounds__(256, 2) void k2_mma()
{
    __shared__ uint32_t adj_hs[2][64 * 36];   // 18.4 KB
    __shared__ float v_s[HH * EMB];           // 8 KB

    int t = threadIdx.x;
    int lane = t & 31, h = t >> 5;
    int gid = lane >> 2, tig = lane & 3;
    int i0 = blockIdx.x * 64, b = blockIdx.y;

#pragma unroll
    for (int p = 0; p < 8; p++) v_s[p * 256 + t] = g_v[p * 256 + t];

    const __half* adjhb = g_adjh + (size_t)b * NN * NN;
    const __half* whT = g_WhTh + (size_t)((b * HH + h) * DD) * NN;
    const float* c1p  = g_c1 + (b * HH + h) * NN + i0;

    uint32_t clb[4][2];
#pragma unroll
    for (int mt = 0; mt < 4; mt++) {
        clb[mt][0] = f2h2b(c1p[mt * 16 + gid]     * LOG2E);
        clb[mt][1] = f2h2b(c1p[mt * 16 + gid + 8] * LOG2E);
    }

    float acc[4][4][4];
    uint32_t z2a[4], z2b[4];
    float zf0[4], zf1[4];
#pragma unroll
    for (int mt = 0; mt < 4; mt++) {
        z2a[mt] = 0u; z2b[mt] = 0u; zf0[mt] = 0.f; zf1[mt] = 0.f;
#pragma unroll
        for (int nt = 0; nt < 4; nt++)
#pragma unroll
            for (int r = 0; r < 4; r++) acc[mt][nt][r] = 0.f;
    }

    uint32_t sbase = smem_u32(adj_hs);

    // tile row = 128 B of half; 8 x 16B chunks; 512 chunks / 256 thr = 2 per thread
#define PREFETCH(tile, buf) do { \
        uint32_t dst0 = sbase + (buf) * (64 * 36 * 4); \
        const __half* srcb = adjhb + (size_t)i0 * NN + (tile) * 64; \
        _Pragma("unroll") \
        for (int p = 0; p < 2; p++) { \
            int idx = p * 256 + t; \
            int row = idx >> 3, c = idx & 7; \
            CP_ASYNC16(dst0 + (row * 36 + c * 4) * 4, \
                       srcb + (size_t)row * NN + c * 8); \
        } \
        CP_COMMIT(); \
    } while (0)

    PREFETCH(0, 0);

#pragma unroll 1
    for (int tile = 0; tile < 16; tile++) {
        if (tile + 1 < 16) { PREFETCH(tile + 1, (tile + 1) & 1); CP_WAIT(1); }
        else               { CP_WAIT(0); }
        __syncthreads();
        const uint32_t* As = adj_hs[tile & 1];

#pragma unroll
        for (int ks = 0; ks < 4; ks++) {
            int kg = tile * 64 + ks * 16;
            uint32_t b0[4], b1[4];
            const __half* Bp = whT + (size_t)gid * NN + kg + 2 * tig;
#pragma unroll
            for (int nt = 0; nt < 4; nt++) {
                b0[nt] = *(const uint32_t*)(Bp + (size_t)nt * 8 * NN);
                b1[nt] = *(const uint32_t*)(Bp + (size_t)nt * 8 * NN + 8);
            }
            const uint32_t* base = As + ks * 8 + tig;
#pragma unroll
            for (int mt = 0; mt < 4; mt++) {
                int rb = mt * 16 + gid;
                uint32_t al0 = base[rb * 36];
                uint32_t al1 = base[(rb + 8) * 36];
                uint32_t ah0 = base[rb * 36 + 4];
                uint32_t ah1 = base[(rb + 8) * 36 + 4];
                uint32_t a0 = h2exp2_u(h2mul_u(clb[mt][0], al0));
                uint32_t a1 = h2exp2_u(h2mul_u(clb[mt][1], al1));
                uint32_t a2 = h2exp2_u(h2mul_u(clb[mt][0], ah0));
                uint32_t a3 = h2exp2_u(h2mul_u(clb[mt][1], ah1));
                z2a[mt] = h2add_u(z2a[mt], h2add_u(a0, a2));
                z2b[mt] = h2add_u(z2b[mt], h2add_u(a1, a3));
#pragma unroll
                for (int nt = 0; nt < 4; nt++)
                    MMA_F16(acc[mt][nt], a0, a1, a2, a3, b0[nt], b1[nt]);
            }
        }
#pragma unroll
        for (int mt = 0; mt < 4; mt++) {
            float2 fa = h22f2(z2a[mt]); zf0[mt] += fa.x + fa.y; z2a[mt] = 0u;
            float2 fb = h22f2(z2b[mt]); zf1[mt] += fb.x + fb.y; z2b[mt] = 0u;
        }
        __syncthreads();
    }
#undef PREFETCH

#pragma unroll
    for (int mt = 0; mt < 4; mt++) {
        zf0[mt] += __shfl_xor_sync(0xffffffffu, zf0[mt], 1);
        zf0[mt] += __shfl_xor_sync(0xffffffffu, zf0[mt], 2);
        zf1[mt] += __shfl_xor_sync(0xffffffffu, zf1[mt], 1);
        zf1[mt] += __shfl_xor_sync(0xffffffffu, zf1[mt], 2);
    }

#pragma unroll
    for (int mt = 0; mt < 4; mt++) {
        float zi0 = 1.f / zf0[mt], zi1 = 1.f / zf1[mt];

        int r0 = i0 + mt * 16 + gid;
        float* o0 = g_h1 + ((size_t)(b * NN + r0)) * EMB + h * 32;
        float* o1 = o0 + (size_t)8 * EMB;
        float q0[4][2], q1[4][2];
#pragma unroll
        for (int nt = 0; nt < 4; nt++) {
            q0[nt][0] = acc[mt][nt][0] * zi0; q0[nt][1] = acc[mt][nt][1] * zi0;
            q1[nt][0] = acc[mt][nt][2] * zi1; q1[nt][1] = acc[mt][nt][3] * zi1;
            *(float2*)(o0 + nt * 8 + 2 * tig) = make_float2(q0[nt][0], q0[nt][1]);
            *(float2*)(o1 + nt * 8 + 2 * tig) = make_float2(q1[nt][0], q1[nt][1]);
        }
#pragma unroll
        for (int th = 0; th < HH; th++) {
            float p0 = 0.f, p1 = 0.f;
#pragma unroll
            for (int nt = 0; nt < 4; nt++) {
                float2 vv = *(const float2*)&v_s[th * 256 + h * 32 + nt * 8 + 2 * tig];
                p0 += q0[nt][0] * vv.x + q0[nt][1] * vv.y;
                p1 += q1[nt][0] * vv.x + q1[nt][1] * vv.y;
            }
            p0 += __shfl_xor_sync(0xffffffffu, p0, 1);
            p0 += __shfl_xor_sync(0xffffffffu, p0, 2);
            p1 += __shfl_xor_sync(0xffffffffu, p1, 1);
            p1 += __shfl_xor_sync(0xffffffffu, p1, 2);
            if (tig == 0) {
                atomicAdd(&g_c2[(b * HH + th) * NN + r0], p0);
                atomicAdd(&g_c2[(b * HH + th) * NN + r0 + 8], p1);
            }
        }
    }
}

// ---------------- K4: finalize c2; Z via Taylor; ziS; S0 ----------------
__global__ __launch_bounds__(256) void k4_z()
{
    int idx = blockIdx.x * 256 + threadIdx.x;
    int n = idx & (NN - 1);
    int h = (idx >> 10) & (HH - 1);
    int b = idx >> 13;

    float raw = g_c2[idx] + g_cb[h];
    float c = raw > 0.f ? raw : 0.01f * raw;
    g_c2[idx] = c;

    float4 R = g_R4[b * NN + n];
    float R5 = g_R5[b * NN + n];
    float Z = 1024.f + c * (R.x + c * (0.5f * R.y + c * ((1.f / 6.f) * R.z
                + c * ((1.f / 24.f) * R.w + c * ((1.f / 120.f) * R5)))));
    float ziS = 1024.f / Z;
    g_zi[idx] = ziS;

    float s = ziS;
#pragma unroll
    for (int off = 16; off; off >>= 1) s += __shfl_xor_sync(0xffffffffu, s, off);
    if ((threadIdx.x & 31) == 0) atomicAdd(&g_s0[b * HH + h], s);
}

// ---------------- K5a: column sums via Taylor Horner on half adj ----------------
// grid (4 jblk, 4 iblk, 16 b), 256 thr. Thread: one j-pair (half2), 128 i's.
__global__ __launch_bounds__(256) void k5a_colsum()
{
    __shared__ uint4 w4s[HH][256];   // per-head broadcast weights, 32 KB
    int b = blockIdx.z, j0 = blockIdx.x * 256, i0 = blockIdx.y * 256;
    int t = threadIdx.x;
    {
        int i = i0 + t;
#pragma unroll
        for (int h = 0; h < HH; h++) {
            float c = g_c2[(b * HH + h) * NN + i];
            float z = g_zi[(b * HH + h) * NN + i];
            float w1 = z * c;
            float w2 = w1 * c * 0.5f;
            float w3 = w2 * c * (1.f / 3.f);
            float w4 = w3 * c * 0.25f;
            w4s[h][t] = make_uint4(f2h2b(w1), f2h2b(w2), f2h2b(w3), f2h2b(w4));
        }
    }
    __syncthreads();

    int jp = t & 127;   // j-pair index
    int iq = t >> 7;    // i half
    const __half* colp = g_adjh + ((size_t)(b * NN + i0 + iq * 128)) * NN + j0 + 2 * jp;

    float gf0[HH], gf1[HH];
#pragma unroll
    for (int h = 0; h < HH; h++) { gf0[h] = 0.f; gf1[h] = 0.f; }

#pragma unroll 1
    for (int ib = 0; ib < 8; ib++) {
        uint32_t ac[HH];
#pragma unroll
        for (int h = 0; h < HH; h++) ac[h] = 0u;
#pragma unroll
        for (int ii = 0; ii < 16; ii++) {
            int i = ib * 16 + ii;
            uint32_t a2 = *(const uint32_t*)(colp + (size_t)i * NN);
#pragma unroll
            for (int h = 0; h < HH; h++) {
                uint4 w = w4s[h][iq * 128 + i];
                uint32_t q = h2fma_u(w.w, a2, w.z);
                q = h2fma_u(q, a2, w.y);
                q = h2fma_u(q, a2, w.x);
                q = h2mul_u(q, a2);
                ac[h] = h2add_u(ac[h], q);
            }
        }
#pragma unroll
        for (int h = 0; h < HH; h++) {
            float2 f = h22f2(ac[h]);
            gf0[h] += f.x; gf1[h] += f.y;
        }
    }
#pragma unroll
    for (int h = 0; h < HH; h++) {
        atomicAdd(&g_g[(b * HH + h) * NN + j0 + 2 * jp],     gf0[h]);
        atomicAdd(&g_g[(b * HH + h) * NN + j0 + 2 * jp + 1], gf1[h]);
    }
}

// ---------------- K5b: u = sum_j g_j * h1_j ; p = u@Wm + 1024*bm ----------------
__global__ __launch_bounds__(256) void k5b_pool(
    const float* __restrict__ Wm, const float* __restrict__ bm)
{
    __shared__ float g_sm[NN];
    __shared__ float u_s[EMB];
    __shared__ float red[8][32];
    int b = blockIdx.y, h = blockIdx.x;
    int t = threadIdx.x;

    float s0 = g_s0[b * HH + h];
#pragma unroll
    for (int p = 0; p < 4; p++)
        g_sm[p * 256 + t] = (g_g[(b * HH + h) * NN + p * 256 + t] + s0) * (1.f / 1024.f);
    __syncthreads();

    float u = 0.f;
    const float* h1p = g_h1 + (size_t)b * NN * EMB + t;
#pragma unroll 4
    for (int j = 0; j < NN; j++)
        u += g_sm[j] * h1p[(size_t)j * EMB];
    u_s[t] = u;
    __syncthreads();

    int d = t & 31, slice = t >> 5;
    const float* wm = Wm + h * EMB * DD;
    float acc = 0.f;
#pragma unroll
    for (int kk = 0; kk < 32; kk++) {
        int k = slice * 32 + kk;
        acc += u_s[k] * wm[k * DD + d];
    }
    red[slice][d] = acc;
    __syncthreads();
    if (t < 32) {
        float s = 0.f;
#pragma unroll
        for (int sl = 0; sl < 8; sl++) s += red[sl][t];
        g_p[b * EMB + h * DD + t] = s + 1024.f * bm[h * DD + t];
    }
}

// ---------------- K6: final MLP head ----------------
__global__ __launch_bounds__(256) void k6_mlp(
    const float* __restrict__ Wp, const float* __restrict__ bp,
    const float* __restrict__ gamma, const float* __restrict__ beta,
    const float* __restrict__ rmean, const float* __restrict__ rvar,
    const float* __restrict__ W1, const float* __restrict__ b1,
    const float* __restrict__ W2, const float* __restrict__ b2,
    float* __restrict__ out)
{
    __shared__ float p_s[256];
    __shared__ float y_s[512];
    __shared__ float z_s[256];
    __shared__ float w_s[128];
    int b = blockIdx.x, t = threadIdx.x;

    p_s[t] = g_p[b * EMB + t];
    __syncthreads();
#pragma unroll
    for (int r = 0; r < 2; r++) {
        int o = r * 256 + t;
        float acc = bp[o];
#pragma unroll 4
        for (int k = 0; k < 256; k++) acc += p_s[k] * Wp[k * 512 + o];
        acc = (acc - rmean[o]) * rsqrtf(rvar[o] + 1e-5f) * gamma[o] + beta[o];
        y_s[o] = fmaxf(acc, 0.f);
    }
    __syncthreads();
    {
        float acc = b1[t];
#pragma unroll 4
        for (int k = 0; k < 512; k++) acc += y_s[k] * W1[k * 256 + t];
        z_s[t] = fmaxf(acc, 0.f);
    }
    __syncthreads();
    if (t < 128) {
        float acc = b2[t];
#pragma unroll 4
        for (int k = 0; k < 256; k++) acc += z_s[k] * W2[k * 128 + t];
        w_s[t] = fmaxf(acc, 0.f);
    }
    __syncthreads();
    if (t < 64) w_s[t] += w_s[t + 64];
    __syncthreads();
    if (t < 32) {
        float v = w_s[t] + w_s[t + 32];
#pragma unroll
        for (int off = 16; off; off >>= 1) v += __shfl_xor_sync(0xffffffffu, v, off);
        if (t == 0) out[b] = v * (1.f / 128.f);
    }
}

// ---------------- launch ----------------
extern "C" void kernel_launch(void* const* d_in, const int* in_sizes, int n_in,
                              void* d_out, int out_size)
{
    const float* x     = (const float*)d_in[0];
    const float* adj   = (const float*)d_in[1];
    const float* Ws    = (const float*)d_in[2];
    const float* bs    = (const float*)d_in[3];
    const float* qs    = (const float*)d_in[4];
    const float* qbs   = (const float*)d_in[5];
    const float* Wm    = (const float*)d_in[6];
    const float* bm    = (const float*)d_in[7];
    const float* qm    = (const float*)d_in[8];
    const float* qbm   = (const float*)d_in[9];
    const float* Wp    = (const float*)d_in[10];
    const float* bp    = (const float*)d_in[11];
    const float* gamma = (const float*)d_in[12];
    const float* beta  = (const float*)d_in[13];
    const float* rmean = (const float*)d_in[14];
    const float* rvar  = (const float*)d_in[15];
    const float* W1    = (const float*)d_in[16];
    const float* b1    = (const float*)d_in[17];
    const float* W2    = (const float*)d_in[18];
    const float* b2    = (const float*)d_in[19];
    float* out = (float*)d_out;

    k1_wh1<<<(BB * HH * NN) / 256, 256>>>(x, Ws, bs, qs, qbs);
    k3v<<<256, 256>>>(Wm, bm, qm, qbm);
    kC_conv<<<dim3(NN / 8, BB), 256>>>(adj);
    k2_mma<<<dim3(NN / 64, BB), 256>>>();             // 4th launch -> ncu target
    k4_z<<<(BB * HH * NN) / 256, 256>>>();
    k5a_colsum<<<dim3(4, 4, BB), 256>>>();
    k5b_pool<<<dim3(HH, BB), 256>>>(Wm, bm);
    k6_mlp<<<BB, 256>>>(Wp, bp, gamma, beta, rmean, rvar, W1, b1, W2, b2, out);
}

// round 7
// speedup vs baseline: 2.6894x; 1.1349x over previous
#include <cuda_runtime.h>
#include <cuda_fp16.h>
#include <cstdint>
#include <cstddef>

// Shapes
#define BB   16
#define NN   1024
#define FIN  7
#define HH   8
#define DD   32
#define EMB  256
#define LOG2E 1.4426950408889634f

// ---------------- scratch ----------------
__device__ __half g_adjh[BB * NN * NN];       // half adj, 32 MB
__device__ uint4  g_Bf4 [BB * HH * 64 * 64];  // frag-packed Wh, 8 MB
__device__ float g_c1 [BB * HH * NN];
__device__ float g_h1 [BB * NN * EMB];        // [b][n][h*32+d] 16 MB
__device__ float g_c2 [BB * HH * NN];         // k2 accumulates h1.v
__device__ float g_g  [BB * HH * NN];
__device__ float g_v  [HH * EMB];
__device__ float g_cb [HH];
__device__ float g_u  [BB * HH * EMB];        // pooled per-head u
__device__ float4 g_R4[BB * NN];              // row power sums R1..R4
__device__ float g_R5 [BB * NN];
__device__ float g_s0 [BB * HH];

// ---------------- half2 helpers ----------------
__device__ __forceinline__ uint32_t h2exp2_u(uint32_t x) {
    uint32_t r; asm("ex2.approx.f16x2 %0, %1;" : "=r"(r) : "r"(x)); return r;
}
__device__ __forceinline__ uint32_t h2mul_u(uint32_t a, uint32_t b) {
    uint32_t r; asm("mul.f16x2 %0, %1, %2;" : "=r"(r) : "r"(a), "r"(b)); return r;
}
__device__ __forceinline__ uint32_t h2add_u(uint32_t a, uint32_t b) {
    uint32_t r; asm("add.f16x2 %0, %1, %2;" : "=r"(r) : "r"(a), "r"(b)); return r;
}
__device__ __forceinline__ uint32_t h2fma_u(uint32_t a, uint32_t b, uint32_t c) {
    uint32_t r; asm("fma.rn.f16x2 %0, %1, %2, %3;" : "=r"(r) : "r"(a), "r"(b), "r"(c)); return r;
}
__device__ __forceinline__ uint32_t f22h2_u(float hi, float lo) {
    uint32_t r; asm("cvt.rn.f16x2.f32 %0, %1, %2;" : "=r"(r) : "f"(hi), "f"(lo)); return r;
}
__device__ __forceinline__ uint32_t f2h2b(float a) {
    uint32_t r;
    asm("{ .reg .f16 v; cvt.rn.f16.f32 v, %1; mov.b32 %0, {v, v}; }" : "=r"(r) : "f"(a));
    return r;
}
__device__ __forceinline__ float2 h22f2(uint32_t h) {
    float2 f;
    asm("{ .reg .f16 l, hh; mov.b32 {l, hh}, %2; cvt.f32.f16 %0, l; cvt.f32.f16 %1, hh; }"
        : "=f"(f.x), "=f"(f.y) : "r"(h));
    return f;
}

#define CP_ASYNC16(dst, src) \
    asm volatile("cp.async.cg.shared.global [%0], [%1], 16;" :: "r"(dst), "l"(src) : "memory")
#define CP_COMMIT() asm volatile("cp.async.commit_group;" ::: "memory")
#define CP_WAIT(n)  asm volatile("cp.async.wait_group %0;" :: "n"(n) : "memory")

#define MMA_F16(c, a0, a1, a2, a3, b0, b1) \
    asm volatile("mma.sync.aligned.m16n8k16.row.col.f32.f16.f16.f32 " \
        "{%0,%1,%2,%3}, {%4,%5,%6,%7}, {%8,%9}, {%0,%1,%2,%3};" \
        : "+f"((c)[0]), "+f"((c)[1]), "+f"((c)[2]), "+f"((c)[3]) \
        : "r"(a0), "r"(a1), "r"(a2), "r"(a3), "r"(b0), "r"(b1))

#define LDSM_X4(r0, r1, r2, r3, a) \
    asm volatile("ldmatrix.sync.aligned.m8n8.x4.shared.b16 {%0,%1,%2,%3}, [%4];" \
        : "=r"(r0), "=r"(r1), "=r"(r2), "=r"(r3) : "r"(a))

__device__ __forceinline__ uint32_t smem_u32(const void* p) {
    uint32_t a;
    asm("{ .reg .u64 t; cvta.to.shared.u64 t, %1; cvt.u32.u64 %0, t; }" : "=r"(a) : "l"(p));
    return a;
}

// ---------------- K1: Wh -> frag-packed g_Bf4; c1; zero c2 ----------------
// CTA covers 256 consecutive n within one (b,h).
__global__ __launch_bounds__(256) void k1_wh1(
    const float* __restrict__ x,  const float* __restrict__ Ws,
    const float* __restrict__ bs, const float* __restrict__ qs,
    const float* __restrict__ qbs)
{
    __shared__ __half swh[32][264];   // [d][n_local], stride 264 -> conflict-free repack
    int t = threadIdx.x;
    int idx = blockIdx.x * 256 + t;
    int n = idx & (NN - 1);
    int h = (idx >> 10) & (HH - 1);
    int b = idx >> 13;

    g_c2[idx] = 0.f;

    float xv[FIN];
    const float* xr = x + ((size_t)(b * NN + n)) * FIN;
#pragma unroll
    for (int i = 0; i < FIN; i++) xv[i] = xr[i];

    const float* W = Ws + h * FIN * DD;
    float s = qbs[h];
#pragma unroll
    for (int d = 0; d < DD; d++) {
        float acc = bs[h * DD + d];
#pragma unroll
        for (int i = 0; i < FIN; i++) acc += xv[i] * W[i * DD + d];
        swh[d][t] = __float2half_rn(acc);
        s += acc * (qs[h * 2 * DD + d] + qs[h * 2 * DD + DD + d]);
    }
    g_c1[idx] = s > 0.f ? s : 0.01f * s;
    __syncthreads();

    // repack to MMA B-fragment order
    int lane = t & 31, gid = lane >> 2, tig = lane & 3;
    int ksg_base = (blockIdx.x & 3) * 16;
#pragma unroll
    for (int q = 0; q < 2; q++) {
        int ksg_l = q * 8 + (t >> 5);
        int kb = ksg_l * 16 + 2 * tig;
        uint32_t u0[4], u1[4];
#pragma unroll
        for (int nt = 0; nt < 4; nt++) {
            u0[nt] = *(const uint32_t*)&swh[nt * 8 + gid][kb];
            u1[nt] = *(const uint32_t*)&swh[nt * 8 + gid][kb + 8];
        }
        uint4* dst = g_Bf4 + ((size_t)((b * HH + h) * 64 + ksg_base + ksg_l)) * 64;
        dst[lane]      = make_uint4(u0[0], u1[0], u0[1], u1[1]);
        dst[32 + lane] = make_uint4(u0[2], u1[2], u0[3], u1[3]);
    }
}

// ---------------- K3v: v[h][k]; cb[h] ----------------
__global__ __launch_bounds__(256) void k3v(
    const float* __restrict__ Wm, const float* __restrict__ bm,
    const float* __restrict__ qm, const float* __restrict__ qbm)
{
    int wg = blockIdx.x * 8 + (threadIdx.x >> 5);
    int lane = threadIdx.x & 31;
    int h = wg >> 8, k = wg & 255;

    float q = qm[h * 64 + lane] + qm[h * 64 + 32 + lane];
    float s = Wm[((size_t)(h * EMB + k)) * DD + lane] * q;
#pragma unroll
    for (int off = 16; off; off >>= 1) s += __shfl_xor_sync(0xffffffffu, s, off);
    if (lane == 0) g_v[h * EMB + k] = s;

    if (blockIdx.x == 0) {
        int w = threadIdx.x >> 5;
        float q2 = qm[w * 64 + lane] + qm[w * 64 + 32 + lane];
        float s2 = bm[w * DD + lane] * q2;
#pragma unroll
        for (int off = 16; off; off >>= 1) s2 += __shfl_xor_sync(0xffffffffu, s2, off);
        if (lane == 0) g_cb[w] = s2 + qbm[w];
    }
}

// ---------------- kC: adj -> half; R1..R5; zero g_g, g_s0, g_u ----------------
__global__ __launch_bounds__(256) void kC_conv(const float* __restrict__ adj)
{
    int b = blockIdx.y;
    int t = threadIdx.x;
    if (t < 64) g_g[b * (HH * NN) + blockIdx.x * 64 + t] = 0.f;
    if (blockIdx.x == 0 && b == 0 && t < BB * HH) g_s0[t] = 0.f;
    if (blockIdx.x < 8) g_u[b * (HH * EMB) + blockIdx.x * 256 + t] = 0.f;

    int w = t >> 5, lane = t & 31;
    int i = blockIdx.x * 8 + w;
    const float4* row = (const float4*)(adj + ((size_t)(b * NN + i)) * NN);
    __half* hrow = g_adjh + ((size_t)(b * NN + i)) * NN;

    float r1 = 0.f, r2 = 0.f, r3 = 0.f, r4 = 0.f, r5 = 0.f;
#pragma unroll
    for (int q = 0; q < 8; q++) {
        float4 va = row[q * 32 + lane];
        uint2 pk = make_uint2(f22h2_u(va.y, va.x), f22h2_u(va.w, va.z));
        *(uint2*)(hrow + 4 * (q * 32 + lane)) = pk;
        float vv[4] = {va.x, va.y, va.z, va.w};
#pragma unroll
        for (int e = 0; e < 4; e++) {
            float a = vv[e], a2 = a * a, a3 = a2 * a;
            r1 += a; r2 += a2; r3 += a3; r4 += a2 * a2; r5 += a2 * a3;
        }
    }
#pragma unroll
    for (int off = 16; off; off >>= 1) {
        r1 += __shfl_xor_sync(0xffffffffu, r1, off);
        r2 += __shfl_xor_sync(0xffffffffu, r2, off);
        r3 += __shfl_xor_sync(0xffffffffu, r3, off);
        r4 += __shfl_xor_sync(0xffffffffu, r4, off);
        r5 += __shfl_xor_sync(0xffffffffu, r5, off);
    }
    if (lane == 0) {
        g_R4[b * NN + i] = make_float4(r1, r2, r3, r4);
        g_R5[b * NN + i] = r5;
    }
}

// ---------------- K2: attention via ldmatrix + packed-B mma.sync f16 ----------------
__global__ __launch_bounds__(256, 2) void k2_mma()
{
    __shared__ __align__(16) uint32_t adj_hs[2][64 * 36];   // 18.4 KB
    __shared__ float v_s[HH * EMB];                          // 8 KB

    int t = threadIdx.x;
    int lane = t & 31, h = t >> 5;
    int gid = lane >> 2, tig = lane & 3;
    int i0 = blockIdx.x * 64, b = blockIdx.y;

#pragma unroll
    for (int p = 0; p < 8; p++) v_s[p * 256 + t] = g_v[p * 256 + t];

    const __half* adjhb = g_adjh + (size_t)b * NN * NN;
    const uint4* Bf = g_Bf4 + (size_t)(b * HH + h) * 64 * 64;
    const float* c1p  = g_c1 + (b * HH + h) * NN + i0;

    uint32_t clb[4][2];
#pragma unroll
    for (int mt = 0; mt < 4; mt++) {
        clb[mt][0] = f2h2b(c1p[mt * 16 + gid]     * LOG2E);
        clb[mt][1] = f2h2b(c1p[mt * 16 + gid + 8] * LOG2E);
    }
    uint32_t bz = (gid == 0) ? 0x3C003C00u : 0u;

    float acc[4][4][4];
    float accz[4][4];
#pragma unroll
    for (int mt = 0; mt < 4; mt++) {
#pragma unroll
        for (int r = 0; r < 4; r++) accz[mt][r] = 0.f;
#pragma unroll
        for (int nt = 0; nt < 4; nt++)
#pragma unroll
            for (int r = 0; r < 4; r++) acc[mt][nt][r] = 0.f;
    }

    uint32_t sbase = smem_u32(adj_hs);
    // ldmatrix per-lane offset: row_sel*144 + khalf*16
    uint32_t lane_off = (((lane & 7) + ((lane >> 3) & 1) * 8) * 144) + ((lane >> 4) & 1) * 16;

#define PREFETCH(tile, buf) do { \
        uint32_t dst0 = sbase + (buf) * (64 * 36 * 4); \
        const __half* srcb = adjhb + (size_t)i0 * NN + (tile) * 64; \
        _Pragma("unroll") \
        for (int p = 0; p < 2; p++) { \
            int idx = p * 256 + t; \
            int row = idx >> 3, c = idx & 7; \
            CP_ASYNC16(dst0 + (row * 36 + c * 4) * 4, \
                       srcb + (size_t)row * NN + c * 8); \
        } \
        CP_COMMIT(); \
    } while (0)

    PREFETCH(0, 0);

#pragma unroll 1
    for (int tile = 0; tile < 16; tile++) {
        if (tile + 1 < 16) { PREFETCH(tile + 1, (tile + 1) & 1); CP_WAIT(1); }
        else               { CP_WAIT(0); }
        __syncthreads();
        uint32_t tb = sbase + (tile & 1) * (64 * 36 * 4) + lane_off;

#pragma unroll
        for (int ks = 0; ks < 4; ks++) {
            uint4 rB0 = Bf[(tile * 4 + ks) * 64 + lane];
            uint4 rB1 = Bf[(tile * 4 + ks) * 64 + 32 + lane];
#pragma unroll
            for (int mt = 0; mt < 4; mt++) {
                uint32_t r0, r1, r2, r3;
                LDSM_X4(r0, r1, r2, r3, tb + mt * 2304 + ks * 32);
                uint32_t a0 = h2exp2_u(h2mul_u(clb[mt][0], r0));
                uint32_t a1 = h2exp2_u(h2mul_u(clb[mt][1], r1));
                uint32_t a2 = h2exp2_u(h2mul_u(clb[mt][0], r2));
                uint32_t a3 = h2exp2_u(h2mul_u(clb[mt][1], r3));
                MMA_F16(accz[mt], a0, a1, a2, a3, bz, bz);
                MMA_F16(acc[mt][0], a0, a1, a2, a3, rB0.x, rB0.y);
                MMA_F16(acc[mt][1], a0, a1, a2, a3, rB0.z, rB0.w);
                MMA_F16(acc[mt][2], a0, a1, a2, a3, rB1.x, rB1.y);
                MMA_F16(acc[mt][3], a0, a1, a2, a3, rB1.z, rB1.w);
            }
        }
        __syncthreads();
    }
#undef PREFETCH

#pragma unroll
    for (int mt = 0; mt < 4; mt++) {
        float z0 = __shfl_sync(0xffffffffu, accz[mt][0], lane & ~3);
        float z1 = __shfl_sync(0xffffffffu, accz[mt][2], lane & ~3);
        float zi0 = 1.f / z0, zi1 = 1.f / z1;

        int r0 = i0 + mt * 16 + gid;
        float* o0 = g_h1 + ((size_t)(b * NN + r0)) * EMB + h * 32;
        float* o1 = o0 + (size_t)8 * EMB;
        float q0[4][2], q1[4][2];
#pragma unroll
        for (int nt = 0; nt < 4; nt++) {
            q0[nt][0] = acc[mt][nt][0] * zi0; q0[nt][1] = acc[mt][nt][1] * zi0;
            q1[nt][0] = acc[mt][nt][2] * zi1; q1[nt][1] = acc[mt][nt][3] * zi1;
            *(float2*)(o0 + nt * 8 + 2 * tig) = make_float2(q0[nt][0], q0[nt][1]);
            *(float2*)(o1 + nt * 8 + 2 * tig) = make_float2(q1[nt][0], q1[nt][1]);
        }
#pragma unroll
        for (int th = 0; th < HH; th++) {
            float p0 = 0.f, p1 = 0.f;
#pragma unroll
            for (int nt = 0; nt < 4; nt++) {
                float2 vv = *(const float2*)&v_s[th * 256 + h * 32 + nt * 8 + 2 * tig];
                p0 += q0[nt][0] * vv.x + q0[nt][1] * vv.y;
                p1 += q1[nt][0] * vv.x + q1[nt][1] * vv.y;
            }
            p0 += __shfl_xor_sync(0xffffffffu, p0, 1);
            p0 += __shfl_xor_sync(0xffffffffu, p0, 2);
            p1 += __shfl_xor_sync(0xffffffffu, p1, 1);
            p1 += __shfl_xor_sync(0xffffffffu, p1, 2);
            if (tig == 0) {
                atomicAdd(&g_c2[(b * HH + th) * NN + r0], p0);
                atomicAdd(&g_c2[(b * HH + th) * NN + r0 + 8], p1);
            }
        }
    }
}

// ---------------- K5a: (absorbs k4) Taylor Z + weights; column sums ----------------
__global__ __launch_bounds__(256) void k5a_colsum()
{
    __shared__ uint4 w4s[HH][256];
    int b = blockIdx.z, j0 = blockIdx.x * 256, i0 = blockIdx.y * 256;
    int t = threadIdx.x;
    {
        int i = i0 + t;
        float4 R = g_R4[b * NN + i];
        float R5v = g_R5[b * NN + i];
#pragma unroll
        for (int h = 0; h < HH; h++) {
            float raw = g_c2[(b * HH + h) * NN + i] + g_cb[h];
            float c = raw > 0.f ? raw : 0.01f * raw;
            float Z = 1024.f + c * (R.x + c * (0.5f * R.y + c * ((1.f / 6.f) * R.z
                        + c * ((1.f / 24.f) * R.w + c * ((1.f / 120.f) * R5v)))));
            float z = 1024.f / Z;
            float w1 = z * c;
            float w2 = w1 * c * 0.5f;
            float w3 = w2 * c * (1.f / 3.f);
            float w4 = w3 * c * 0.25f;
            w4s[h][t] = make_uint4(f2h2b(w1), f2h2b(w2), f2h2b(w3), f2h2b(w4));
            if (blockIdx.x == 0) {
                float sv = z;
#pragma unroll
                for (int off = 16; off; off >>= 1)
                    sv += __shfl_xor_sync(0xffffffffu, sv, off);
                if ((t & 31) == 0) atomicAdd(&g_s0[b * HH + h], sv);
            }
        }
    }
    __syncthreads();

    int jp = t & 127, iq = t >> 7;
    const __half* colp = g_adjh + ((size_t)(b * NN + i0 + iq * 128)) * NN + j0 + 2 * jp;

    float gf0[HH], gf1[HH];
#pragma unroll
    for (int h = 0; h < HH; h++) { gf0[h] = 0.f; gf1[h] = 0.f; }

#pragma unroll 1
    for (int ib = 0; ib < 8; ib++) {
        uint32_t ac[HH];
#pragma unroll
        for (int h = 0; h < HH; h++) ac[h] = 0u;
#pragma unroll
        for (int ii = 0; ii < 16; ii++) {
            int i = ib * 16 + ii;
            uint32_t a2 = *(const uint32_t*)(colp + (size_t)i * NN);
#pragma unroll
            for (int h = 0; h < HH; h++) {
                uint4 w = w4s[h][iq * 128 + i];
                uint32_t q = h2fma_u(w.w, a2, w.z);
                q = h2fma_u(q, a2, w.y);
                q = h2fma_u(q, a2, w.x);
                q = h2mul_u(q, a2);
                ac[h] = h2add_u(ac[h], q);
            }
        }
#pragma unroll
        for (int h = 0; h < HH; h++) {
            float2 f = h22f2(ac[h]);
            gf0[h] += f.x; gf1[h] += f.y;
        }
    }
#pragma unroll
    for (int h = 0; h < HH; h++) {
        atomicAdd(&g_g[(b * HH + h) * NN + j0 + 2 * jp],     gf0[h]);
        atomicAdd(&g_g[(b * HH + h) * NN + j0 + 2 * jp + 1], gf1[h]);
    }
}

// ---------------- K5b: partial u = sum_{j in block} gtilde_j * h1_j ----------------
// grid (8 jblk, 16 b), 256 thr. Thread owns feature t; 8 head accumulators.
__global__ __launch_bounds__(256) void k5b_partial()
{
    __shared__ float gt[HH][128];
    int b = blockIdx.y, jb = blockIdx.x * 128;
    int t = threadIdx.x;

#pragma unroll
    for (int p = 0; p < 4; p++) {
        int idx = p * 256 + t;          // 0..1023 = h*128 + j
        int h = idx >> 7, j = idx & 127;
        gt[h][j] = (g_g[(b * HH + h) * NN + jb + j] + g_s0[b * HH + h]) * (1.f / 1024.f);
    }
    __syncthreads();

    float u[HH];
#pragma unroll
    for (int h = 0; h < HH; h++) u[h] = 0.f;

    const float* h1p = g_h1 + ((size_t)(b * NN + jb)) * EMB + t;
#pragma unroll 4
    for (int j = 0; j < 128; j++) {
        float hv = h1p[(size_t)j * EMB];
#pragma unroll
        for (int h = 0; h < HH; h++) u[h] += gt[h][j] * hv;
    }
#pragma unroll
    for (int h = 0; h < HH; h++)
        atomicAdd(&g_u[(b * HH + h) * EMB + t], u[h]);
}

// ---------------- K6: p = u@Wm + 1024*bm, then MLP head ----------------
__global__ __launch_bounds__(256) void k6_mlp(
    const float* __restrict__ Wm, const float* __restrict__ bm,
    const float* __restrict__ Wp, const float* __restrict__ bp,
    const float* __restrict__ gamma, const float* __restrict__ beta,
    const float* __restrict__ rmean, const float* __restrict__ rvar,
    const float* __restrict__ W1, const float* __restrict__ b1,
    const float* __restrict__ W2, const float* __restrict__ b2,
    float* __restrict__ out)
{
    __shared__ float u_sm[HH * EMB];
    __shared__ float p_s[256];
    __shared__ float y_s[512];
    __shared__ float z_s[256];
    __shared__ float w_s[128];
    int b = blockIdx.x, t = threadIdx.x;

#pragma unroll
    for (int p = 0; p < 8; p++) u_sm[p * 256 + t] = g_u[b * (HH * EMB) + p * 256 + t];
    __syncthreads();

    {
        int h = t >> 5, d = t & 31;
        float acc = 1024.f * bm[h * DD + d];
        const float* wm = Wm + (size_t)h * EMB * DD + d;
#pragma unroll 4
        for (int k = 0; k < EMB; k++) acc += u_sm[h * EMB + k] * wm[(size_t)k * DD];
        p_s[t] = acc;
    }
    __syncthreads();

#pragma unroll
    for (int r = 0; r < 2; r++) {
        int o = r * 256 + t;
        float acc = bp[o];
#pragma unroll 4
        for (int k = 0; k < 256; k++) acc += p_s[k] * Wp[k * 512 + o];
        acc = (acc - rmean[o]) * rsqrtf(rvar[o] + 1e-5f) * gamma[o] + beta[o];
        y_s[o] = fmaxf(acc, 0.f);
    }
    __syncthreads();
    {
        float acc = b1[t];
#pragma unroll 4
        for (int k = 0; k < 512; k++) acc += y_s[k] * W1[k * 256 + t];
        z_s[t] = fmaxf(acc, 0.f);
    }
    __syncthreads();
    if (t < 128) {
        float acc = b2[t];
#pragma unroll 4
        for (int k = 0; k < 256; k++) acc += z_s[k] * W2[k * 128 + t];
        w_s[t] = fmaxf(acc, 0.f);
    }
    __syncthreads();
    if (t < 64) w_s[t] += w_s[t + 64];
    __syncthreads();
    if (t < 32) {
        float v = w_s[t] + w_s[t + 32];
#pragma unroll
        for (int off = 16; off; off >>= 1) v += __shfl_xor_sync(0xffffffffu, v, off);
        if (t == 0) out[b] = v * (1.f / 128.f);
    }
}

// ---------------- launch ----------------
extern "C" void kernel_launch(void* const* d_in, const int* in_sizes, int n_in,
                              void* d_out, int out_size)
{
    const float* x     = (const float*)d_in[0];
    const float* adj   = (const float*)d_in[1];
    const float* Ws    = (const float*)d_in[2];
    const float* bs    = (const float*)d_in[3];
    const float* qs    = (const float*)d_in[4];
    const float* qbs   = (const float*)d_in[5];
    const float* Wm    = (const float*)d_in[6];
    const float* bm    = (const float*)d_in[7];
    const float* qm    = (const float*)d_in[8];
    const float* qbm   = (const float*)d_in[9];
    const float* Wp    = (const float*)d_in[10];
    const float* bp    = (const float*)d_in[11];
    const float* gamma = (const float*)d_in[12];
    const float* beta  = (const float*)d_in[13];
    const float* rmean = (const float*)d_in[14];
    const float* rvar  = (const float*)d_in[15];
    const float* W1    = (const float*)d_in[16];
    const float* b1    = (const float*)d_in[17];
    const float* W2    = (const float*)d_in[18];
    const float* b2    = (const float*)d_in[19];
    float* out = (float*)d_out;

    k1_wh1<<<(BB * HH * NN) / 256, 256>>>(x, Ws, bs, qs, qbs);
    k3v<<<256, 256>>>(Wm, bm, qm, qbm);
    kC_conv<<<dim3(NN / 8, BB), 256>>>(adj);
    k2_mma<<<dim3(NN / 64, BB), 256>>>();             // 4th launch -> ncu target
    k5a_colsum<<<dim3(4, 4, BB), 256>>>();
    k5b_partial<<<dim3(8, BB), 256>>>();
    k6_mlp<<<BB, 256>>>(Wm, bm, Wp, bp, gamma, beta, rmean, rvar, W1, b1, W2, b2, out);
}

// round 8
// speedup vs baseline: 2.8035x; 1.0424x over previous
#include <cuda_runtime.h>
#include <cuda_fp16.h>
#include <cstdint>
#include <cstddef>

// Shapes
#define BB   16
#define NN   1024
#define FIN  7
#define HH   8
#define DD   32
#define EMB  256
#define LOG2E 1.4426950408889634f

// ---------------- scratch ----------------
__device__ __half g_adjh[BB * NN * NN];       // half adj, 32 MB
__device__ uint4  g_Bf4 [BB * HH * 64 * 64];  // frag-packed Wh, 8 MB
__device__ uint4  g_wf  [BB * 64 * 64];       // frag-packed Taylor weights, 1 MB
__device__ float g_c1 [BB * HH * NN];
__device__ float g_h1 [BB * NN * EMB];        // [b][n][h*32+d] 16 MB
__device__ float g_c2 [BB * HH * NN];         // k2 accumulates h1.v
__device__ float g_g  [BB * HH * NN];
__device__ float g_v  [HH * EMB];
__device__ float g_cb [HH];
__device__ float g_u  [BB * HH * EMB];        // pooled per-head u
__device__ float4 g_R4[BB * NN];              // row power sums R1..R4
__device__ float g_R5 [BB * NN];
__device__ float g_s0 [BB * HH];

// ---------------- half2 helpers ----------------
__device__ __forceinline__ uint32_t h2exp2_u(uint32_t x) {
    uint32_t r; asm("ex2.approx.f16x2 %0, %1;" : "=r"(r) : "r"(x)); return r;
}
__device__ __forceinline__ uint32_t h2mul_u(uint32_t a, uint32_t b) {
    uint32_t r; asm("mul.f16x2 %0, %1, %2;" : "=r"(r) : "r"(a), "r"(b)); return r;
}
__device__ __forceinline__ uint32_t f22h2_u(float hi, float lo) {
    uint32_t r; asm("cvt.rn.f16x2.f32 %0, %1, %2;" : "=r"(r) : "f"(hi), "f"(lo)); return r;
}
__device__ __forceinline__ uint32_t f2h2b(float a) {
    uint32_t r;
    asm("{ .reg .f16 v; cvt.rn.f16.f32 v, %1; mov.b32 %0, {v, v}; }" : "=r"(r) : "f"(a));
    return r;
}

#define CP_ASYNC16(dst, src) \
    asm volatile("cp.async.cg.shared.global [%0], [%1], 16;" :: "r"(dst), "l"(src) : "memory")
#define CP_COMMIT() asm volatile("cp.async.commit_group;" ::: "memory")
#define CP_WAIT(n)  asm volatile("cp.async.wait_group %0;" :: "n"(n) : "memory")

#define MMA_F16(c, a0, a1, a2, a3, b0, b1) \
    asm volatile("mma.sync.aligned.m16n8k16.row.col.f32.f16.f16.f32 " \
        "{%0,%1,%2,%3}, {%4,%5,%6,%7}, {%8,%9}, {%0,%1,%2,%3};" \
        : "+f"((c)[0]), "+f"((c)[1]), "+f"((c)[2]), "+f"((c)[3]) \
        : "r"(a0), "r"(a1), "r"(a2), "r"(a3), "r"(b0), "r"(b1))

#define LDSM_X4(r0, r1, r2, r3, a) \
    asm volatile("ldmatrix.sync.aligned.m8n8.x4.shared.b16 {%0,%1,%2,%3}, [%4];" \
        : "=r"(r0), "=r"(r1), "=r"(r2), "=r"(r3) : "r"(a))

#define LDSM_X4_T(r0, r1, r2, r3, a) \
    asm volatile("ldmatrix.sync.aligned.m8n8.x4.trans.shared.b16 {%0,%1,%2,%3}, [%4];" \
        : "=r"(r0), "=r"(r1), "=r"(r2), "=r"(r3) : "r"(a))

__device__ __forceinline__ uint32_t smem_u32(const void* p) {
    uint32_t a;
    asm("{ .reg .u64 t; cvta.to.shared.u64 t, %1; cvt.u32.u64 %0, t; }" : "=r"(a) : "l"(p));
    return a;
}

// ---------------- K1: Wh -> frag-packed g_Bf4; c1; zero c2 ----------------
__global__ __launch_bounds__(256) void k1_wh1(
    const float* __restrict__ x,  const float* __restrict__ Ws,
    const float* __restrict__ bs, const float* __restrict__ qs,
    const float* __restrict__ qbs)
{
    __shared__ __half swh[32][264];
    int t = threadIdx.x;
    int idx = blockIdx.x * 256 + t;
    int n = idx & (NN - 1);
    int h = (idx >> 10) & (HH - 1);
    int b = idx >> 13;

    g_c2[idx] = 0.f;

    float xv[FIN];
    const float* xr = x + ((size_t)(b * NN + n)) * FIN;
#pragma unroll
    for (int i = 0; i < FIN; i++) xv[i] = xr[i];

    const float* W = Ws + h * FIN * DD;
    float s = qbs[h];
#pragma unroll
    for (int d = 0; d < DD; d++) {
        float acc = bs[h * DD + d];
#pragma unroll
        for (int i = 0; i < FIN; i++) acc += xv[i] * W[i * DD + d];
        swh[d][t] = __float2half_rn(acc);
        s += acc * (qs[h * 2 * DD + d] + qs[h * 2 * DD + DD + d]);
    }
    g_c1[idx] = s > 0.f ? s : 0.01f * s;
    __syncthreads();

    int lane = t & 31, gid = lane >> 2, tig = lane & 3;
    int ksg_base = (blockIdx.x & 3) * 16;
#pragma unroll
    for (int q = 0; q < 2; q++) {
        int ksg_l = q * 8 + (t >> 5);
        int kb = ksg_l * 16 + 2 * tig;
        uint32_t u0[4], u1[4];
#pragma unroll
        for (int nt = 0; nt < 4; nt++) {
            u0[nt] = *(const uint32_t*)&swh[nt * 8 + gid][kb];
            u1[nt] = *(const uint32_t*)&swh[nt * 8 + gid][kb + 8];
        }
        uint4* dst = g_Bf4 + ((size_t)((b * HH + h) * 64 + ksg_base + ksg_l)) * 64;
        dst[lane]      = make_uint4(u0[0], u1[0], u0[1], u1[1]);
        dst[32 + lane] = make_uint4(u0[2], u1[2], u0[3], u1[3]);
    }
}

// ---------------- K3v: v[h][k]; cb[h] ----------------
__global__ __launch_bounds__(256) void k3v(
    const float* __restrict__ Wm, const float* __restrict__ bm,
    const float* __restrict__ qm, const float* __restrict__ qbm)
{
    int wg = blockIdx.x * 8 + (threadIdx.x >> 5);
    int lane = threadIdx.x & 31;
    int h = wg >> 8, k = wg & 255;

    float q = qm[h * 64 + lane] + qm[h * 64 + 32 + lane];
    float s = Wm[((size_t)(h * EMB + k)) * DD + lane] * q;
#pragma unroll
    for (int off = 16; off; off >>= 1) s += __shfl_xor_sync(0xffffffffu, s, off);
    if (lane == 0) g_v[h * EMB + k] = s;

    if (blockIdx.x == 0) {
        int w = threadIdx.x >> 5;
        float q2 = qm[w * 64 + lane] + qm[w * 64 + 32 + lane];
        float s2 = bm[w * DD + lane] * q2;
#pragma unroll
        for (int off = 16; off; off >>= 1) s2 += __shfl_xor_sync(0xffffffffu, s2, off);
        if (lane == 0) g_cb[w] = s2 + qbm[w];
    }
}

// ---------------- kC: adj -> half; R1..R5; zero g_g, g_s0, g_u ----------------
__global__ __launch_bounds__(256) void kC_conv(const float* __restrict__ adj)
{
    int b = blockIdx.y;
    int t = threadIdx.x;
    if (t < 64) g_g[b * (HH * NN) + blockIdx.x * 64 + t] = 0.f;
    if (blockIdx.x == 0 && b == 0 && t < BB * HH) g_s0[t] = 0.f;
    if (blockIdx.x < 8) g_u[b * (HH * EMB) + blockIdx.x * 256 + t] = 0.f;

    int w = t >> 5, lane = t & 31;
    int i = blockIdx.x * 8 + w;
    const float4* row = (const float4*)(adj + ((size_t)(b * NN + i)) * NN);
    __half* hrow = g_adjh + ((size_t)(b * NN + i)) * NN;

    float r1 = 0.f, r2 = 0.f, r3 = 0.f, r4 = 0.f, r5 = 0.f;
#pragma unroll
    for (int q = 0; q < 8; q++) {
        float4 va = row[q * 32 + lane];
        uint2 pk = make_uint2(f22h2_u(va.y, va.x), f22h2_u(va.w, va.z));
        *(uint2*)(hrow + 4 * (q * 32 + lane)) = pk;
        float vv[4] = {va.x, va.y, va.z, va.w};
#pragma unroll
        for (int e = 0; e < 4; e++) {
            float a = vv[e], a2 = a * a, a3 = a2 * a;
            r1 += a; r2 += a2; r3 += a3; r4 += a2 * a2; r5 += a2 * a3;
        }
    }
#pragma unroll
    for (int off = 16; off; off >>= 1) {
        r1 += __shfl_xor_sync(0xffffffffu, r1, off);
        r2 += __shfl_xor_sync(0xffffffffu, r2, off);
        r3 += __shfl_xor_sync(0xffffffffu, r3, off);
        r4 += __shfl_xor_sync(0xffffffffu, r4, off);
        r5 += __shfl_xor_sync(0xffffffffu, r5, off);
    }
    if (lane == 0) {
        g_R4[b * NN + i] = make_float4(r1, r2, r3, r4);
        g_R5[b * NN + i] = r5;
    }
}

// ---------------- K2: attention via ldmatrix + packed-B mma.sync f16 ----------------
__global__ __launch_bounds__(256, 2) void k2_mma()
{
    __shared__ __align__(16) uint32_t adj_hs[2][64 * 36];
    __shared__ float v_s[HH * EMB];

    int t = threadIdx.x;
    int lane = t & 31, h = t >> 5;
    int gid = lane >> 2, tig = lane & 3;
    int i0 = blockIdx.x * 64, b = blockIdx.y;

#pragma unroll
    for (int p = 0; p < 8; p++) v_s[p * 256 + t] = g_v[p * 256 + t];

    const __half* adjhb = g_adjh + (size_t)b * NN * NN;
    const uint4* Bf = g_Bf4 + (size_t)(b * HH + h) * 64 * 64;
    const float* c1p  = g_c1 + (b * HH + h) * NN + i0;

    uint32_t clb[4][2];
#pragma unroll
    for (int mt = 0; mt < 4; mt++) {
        clb[mt][0] = f2h2b(c1p[mt * 16 + gid]     * LOG2E);
        clb[mt][1] = f2h2b(c1p[mt * 16 + gid + 8] * LOG2E);
    }
    uint32_t bz = (gid == 0) ? 0x3C003C00u : 0u;

    float acc[4][4][4];
    float accz[4][4];
#pragma unroll
    for (int mt = 0; mt < 4; mt++) {
#pragma unroll
        for (int r = 0; r < 4; r++) accz[mt][r] = 0.f;
#pragma unroll
        for (int nt = 0; nt < 4; nt++)
#pragma unroll
            for (int r = 0; r < 4; r++) acc[mt][nt][r] = 0.f;
    }

    uint32_t sbase = smem_u32(adj_hs);
    uint32_t lane_off = (((lane & 7) + ((lane >> 3) & 1) * 8) * 144) + ((lane >> 4) & 1) * 16;

#define PREFETCH(tile, buf) do { \
        uint32_t dst0 = sbase + (buf) * (64 * 36 * 4); \
        const __half* srcb = adjhb + (size_t)i0 * NN + (tile) * 64; \
        _Pragma("unroll") \
        for (int p = 0; p < 2; p++) { \
            int idx = p * 256 + t; \
            int row = idx >> 3, c = idx & 7; \
            CP_ASYNC16(dst0 + (row * 36 + c * 4) * 4, \
                       srcb + (size_t)row * NN + c * 8); \
        } \
        CP_COMMIT(); \
    } while (0)

    PREFETCH(0, 0);

#pragma unroll 1
    for (int tile = 0; tile < 16; tile++) {
        if (tile + 1 < 16) { PREFETCH(tile + 1, (tile + 1) & 1); CP_WAIT(1); }
        else               { CP_WAIT(0); }
        __syncthreads();
        uint32_t tb = sbase + (tile & 1) * (64 * 36 * 4) + lane_off;

#pragma unroll
        for (int ks = 0; ks < 4; ks++) {
            uint4 rB0 = Bf[(tile * 4 + ks) * 64 + lane];
            uint4 rB1 = Bf[(tile * 4 + ks) * 64 + 32 + lane];
#pragma unroll
            for (int mt = 0; mt < 4; mt++) {
                uint32_t r0, r1, r2, r3;
                LDSM_X4(r0, r1, r2, r3, tb + mt * 2304 + ks * 32);
                uint32_t a0 = h2exp2_u(h2mul_u(clb[mt][0], r0));
                uint32_t a1 = h2exp2_u(h2mul_u(clb[mt][1], r1));
                uint32_t a2 = h2exp2_u(h2mul_u(clb[mt][0], r2));
                uint32_t a3 = h2exp2_u(h2mul_u(clb[mt][1], r3));
                MMA_F16(accz[mt], a0, a1, a2, a3, bz, bz);
                MMA_F16(acc[mt][0], a0, a1, a2, a3, rB0.x, rB0.y);
                MMA_F16(acc[mt][1], a0, a1, a2, a3, rB0.z, rB0.w);
                MMA_F16(acc[mt][2], a0, a1, a2, a3, rB1.x, rB1.y);
                MMA_F16(acc[mt][3], a0, a1, a2, a3, rB1.z, rB1.w);
            }
        }
        __syncthreads();
    }
#undef PREFETCH

#pragma unroll
    for (int mt = 0; mt < 4; mt++) {
        float z0 = __shfl_sync(0xffffffffu, accz[mt][0], lane & ~3);
        float z1 = __shfl_sync(0xffffffffu, accz[mt][2], lane & ~3);
        float zi0 = 1.f / z0, zi1 = 1.f / z1;

        int r0 = i0 + mt * 16 + gid;
        float* o0 = g_h1 + ((size_t)(b * NN + r0)) * EMB + h * 32;
        float* o1 = o0 + (size_t)8 * EMB;
        float q0[4][2], q1[4][2];
#pragma unroll
        for (int nt = 0; nt < 4; nt++) {
            q0[nt][0] = acc[mt][nt][0] * zi0; q0[nt][1] = acc[mt][nt][1] * zi0;
            q1[nt][0] = acc[mt][nt][2] * zi1; q1[nt][1] = acc[mt][nt][3] * zi1;
            *(float2*)(o0 + nt * 8 + 2 * tig) = make_float2(q0[nt][0], q0[nt][1]);
            *(float2*)(o1 + nt * 8 + 2 * tig) = make_float2(q1[nt][0], q1[nt][1]);
        }
#pragma unroll
        for (int th = 0; th < HH; th++) {
            float p0 = 0.f, p1 = 0.f;
#pragma unroll
            for (int nt = 0; nt < 4; nt++) {
                float2 vv = *(const float2*)&v_s[th * 256 + h * 32 + nt * 8 + 2 * tig];
                p0 += q0[nt][0] * vv.x + q0[nt][1] * vv.y;
                p1 += q1[nt][0] * vv.x + q1[nt][1] * vv.y;
            }
            p0 += __shfl_xor_sync(0xffffffffu, p0, 1);
            p0 += __shfl_xor_sync(0xffffffffu, p0, 2);
            p1 += __shfl_xor_sync(0xffffffffu, p1, 1);
            p1 += __shfl_xor_sync(0xffffffffu, p1, 2);
            if (tig == 0) {
                atomicAdd(&g_c2[(b * HH + th) * NN + r0], p0);
                atomicAdd(&g_c2[(b * HH + th) * NN + r0 + 8], p1);
            }
        }
    }
}

// ---------------- K4w: Taylor weights -> MMA B-frag layout; S0 ----------------
// warp per (b, ig=i/16). lane: tig = l&3, h = l>>2.
__global__ __launch_bounds__(256) void k4_wfrag()
{
    int wg = blockIdx.x * 8 + (threadIdx.x >> 5);   // (b, ig)
    int lane = threadIdx.x & 31;
    int b = wg >> 6, ig = wg & 63;
    int i0 = ig * 16;
    int tig = lane & 3, h = lane >> 2;
    float cbv = g_cb[h];

    int iarr[4] = {i0 + 2 * tig, i0 + 2 * tig + 1, i0 + 8 + 2 * tig, i0 + 9 + 2 * tig};
    float w[4][4];
    float s0p = 0.f;
#pragma unroll
    for (int q = 0; q < 4; q++) {
        int i = iarr[q];
        float raw = g_c2[(b * HH + h) * NN + i] + cbv;
        float c = raw > 0.f ? raw : 0.01f * raw;
        float4 R = g_R4[b * NN + i];
        float R5v = g_R5[b * NN + i];
        float Z = 1024.f + c * (R.x + c * (0.5f * R.y + c * ((1.f / 6.f) * R.z
                    + c * ((1.f / 24.f) * R.w + c * ((1.f / 120.f) * R5v)))));
        float z = 1024.f / Z;
        s0p += z;
        w[q][0] = z * c;
        w[q][1] = w[q][0] * c * 0.5f;
        w[q][2] = w[q][1] * c * (1.f / 3.f);
        w[q][3] = w[q][2] * c * 0.25f;
    }
    uint4 p0 = make_uint4(f22h2_u(w[1][0], w[0][0]), f22h2_u(w[3][0], w[2][0]),
                          f22h2_u(w[1][1], w[0][1]), f22h2_u(w[3][1], w[2][1]));
    uint4 p1 = make_uint4(f22h2_u(w[1][2], w[0][2]), f22h2_u(w[3][2], w[2][2]),
                          f22h2_u(w[1][3], w[0][3]), f22h2_u(w[3][3], w[2][3]));
    uint4* dst = g_wf + ((size_t)(b * 64 + ig)) * 64;
    dst[lane * 2]     = p0;
    dst[lane * 2 + 1] = p1;

    s0p += __shfl_xor_sync(0xffffffffu, s0p, 1);
    s0p += __shfl_xor_sync(0xffffffffu, s0p, 2);
    if (tig == 0) atomicAdd(&g_s0[b * HH + h], s0p);
}

// ---------------- K5a: column sums as MMA: D[j,h] += (A^m)^T x W_m ----------------
// grid (8 jblk, 4 isplit, 16 b), 256 thr, warp owns 16 j.
__global__ __launch_bounds__(256) void k5a_mma()
{
    __shared__ __align__(16) uint32_t at[2][16 * 68];   // 16 rows x 68 words, stride 272B

    int t = threadIdx.x, lane = t & 31, w = t >> 5;
    int jb = blockIdx.x, iq = blockIdx.y, b = blockIdx.z;
    int j0 = jb * 128, i0c = iq * 256;
    int jw = w * 16;

    const __half* adjb = g_adjh + (size_t)b * NN * NN;
    uint32_t sbase = smem_u32(at);

    // ldmatrix.trans lane addressing (4 groups of 8)
    int grp = lane >> 3, r = lane & 7;
    int row = (grp >= 2) ? 8 + r : r;
    int colh = ((grp & 1) ? jw + 8 : jw);
    uint32_t loff = (uint32_t)(row * 272 + colh * 2);

    float acc[4] = {0.f, 0.f, 0.f, 0.f};

#define PRE5(step, buf) do { \
        uint32_t dst0 = sbase + (buf) * (16 * 68 * 4); \
        const __half* srcb = adjb + (size_t)(i0c + (step) * 16) * NN + j0; \
        int rw = t >> 4, c = t & 15; \
        CP_ASYNC16(dst0 + rw * 272 + c * 16, srcb + (size_t)rw * NN + c * 8); \
        CP_COMMIT(); \
    } while (0)

    PRE5(0, 0);

#pragma unroll 1
    for (int step = 0; step < 16; step++) {
        if (step + 1 < 16) { PRE5(step + 1, (step + 1) & 1); CP_WAIT(1); }
        else               { CP_WAIT(0); }
        __syncthreads();

        const uint4* wfp = g_wf + ((size_t)(b * 64 + (i0c >> 4) + step)) * 64;
        uint4 p0 = wfp[lane * 2];
        uint4 p1 = wfp[lane * 2 + 1];

        uint32_t a1[4];
        LDSM_X4_T(a1[0], a1[1], a1[2], a1[3],
                  sbase + (step & 1) * (16 * 68 * 4) + loff);
        uint32_t a2[4], a3[4], a4[4];
#pragma unroll
        for (int q = 0; q < 4; q++) {
            a2[q] = h2mul_u(a1[q], a1[q]);
            a3[q] = h2mul_u(a2[q], a1[q]);
            a4[q] = h2mul_u(a2[q], a2[q]);
        }
        MMA_F16(acc, a1[0], a1[1], a1[2], a1[3], p0.x, p0.y);
        MMA_F16(acc, a2[0], a2[1], a2[2], a2[3], p0.z, p0.w);
        MMA_F16(acc, a3[0], a3[1], a3[2], a3[3], p1.x, p1.y);
        MMA_F16(acc, a4[0], a4[1], a4[2], a4[3], p1.z, p1.w);
        __syncthreads();
    }
#undef PRE5

    // D layout: c0,c1 -> row lane/4, cols 2*(lane%4), +1 ; c2,c3 -> row+8
    int jg1 = j0 + jw + (lane >> 2);
    int jg2 = jg1 + 8;
    int hc = 2 * (lane & 3);
    atomicAdd(&g_g[(b * HH + hc)     * NN + jg1], acc[0]);
    atomicAdd(&g_g[(b * HH + hc + 1) * NN + jg1], acc[1]);
    atomicAdd(&g_g[(b * HH + hc)     * NN + jg2], acc[2]);
    atomicAdd(&g_g[(b * HH + hc + 1) * NN + jg2], acc[3]);
}

// ---------------- K5b: partial u = sum_{j in block} gtilde_j * h1_j ----------------
__global__ __launch_bounds__(256) void k5b_partial()
{
    __shared__ float gt[HH][128];
    int b = blockIdx.y, jb = blockIdx.x * 128;
    int t = threadIdx.x;

#pragma unroll
    for (int p = 0; p < 4; p++) {
        int idx = p * 256 + t;
        int h = idx >> 7, j = idx & 127;
        gt[h][j] = (g_g[(b * HH + h) * NN + jb + j] + g_s0[b * HH + h]) * (1.f / 1024.f);
    }
    __syncthreads();

    float u[HH];
#pragma unroll
    for (int h = 0; h < HH; h++) u[h] = 0.f;

    const float* h1p = g_h1 + ((size_t)(b * NN + jb)) * EMB + t;
#pragma unroll 4
    for (int j = 0; j < 128; j++) {
        float hv = h1p[(size_t)j * EMB];
#pragma unroll
        for (int h = 0; h < HH; h++) u[h] += gt[h][j] * hv;
    }
#pragma unroll
    for (int h = 0; h < HH; h++)
        atomicAdd(&g_u[(b * HH + h) * EMB + t], u[h]);
}

// ---------------- K6: p = u@Wm + 1024*bm, then MLP head ----------------
__global__ __launch_bounds__(256) void k6_mlp(
    const float* __restrict__ Wm, const float* __restrict__ bm,
    const float* __restrict__ Wp, const float* __restrict__ bp,
    const float* __restrict__ gamma, const float* __restrict__ beta,
    const float* __restrict__ rmean, const float* __restrict__ rvar,
    const float* __restrict__ W1, const float* __restrict__ b1,
    const float* __restrict__ W2, const float* __restrict__ b2,
    float* __restrict__ out)
{
    __shared__ float u_sm[HH * EMB];
    __shared__ float p_s[256];
    __shared__ float y_s[512];
    __shared__ float z_s[256];
    __shared__ float w_s[128];
    int b = blockIdx.x, t = threadIdx.x;

#pragma unroll
    for (int p = 0; p < 8; p++) u_sm[p * 256 + t] = g_u[b * (HH * EMB) + p * 256 + t];
    __syncthreads();

    {
        int h = t >> 5, d = t & 31;
        float acc = 1024.f * bm[h * DD + d];
        const float* wm = Wm + (size_t)h * EMB * DD + d;
#pragma unroll 4
        for (int k = 0; k < EMB; k++) acc += u_sm[h * EMB + k] * wm[(size_t)k * DD];
        p_s[t] = acc;
    }
    __syncthreads();

#pragma unroll
    for (int r = 0; r < 2; r++) {
        int o = r * 256 + t;
        float acc = bp[o];
#pragma unroll 4
        for (int k = 0; k < 256; k++) acc += p_s[k] * Wp[k * 512 + o];
        acc = (acc - rmean[o]) * rsqrtf(rvar[o] + 1e-5f) * gamma[o] + beta[o];
        y_s[o] = fmaxf(acc, 0.f);
    }
    __syncthreads();
    {
        float acc = b1[t];
#pragma unroll 4
        for (int k = 0; k < 512; k++) acc += y_s[k] * W1[k * 256 + t];
        z_s[t] = fmaxf(acc, 0.f);
    }
    __syncthreads();
    if (t < 128) {
        float acc = b2[t];
#pragma unroll 4
        for (int k = 0; k < 256; k++) acc += z_s[k] * W2[k * 128 + t];
        w_s[t] = fmaxf(acc, 0.f);
    }
    __syncthreads();
    if (t < 64) w_s[t] += w_s[t + 64];
    __syncthreads();
    if (t < 32) {
        float v = w_s[t] + w_s[t + 32];
#pragma unroll
        for (int off = 16; off; off >>= 1) v += __shfl_xor_sync(0xffffffffu, v, off);
        if (t == 0) out[b] = v * (1.f / 128.f);
    }
}

// ---------------- launch ----------------
extern "C" void kernel_launch(void* const* d_in, const int* in_sizes, int n_in,
                              void* d_out, int out_size)
{
    const float* x     = (const float*)d_in[0];
    const float* adj   = (const float*)d_in[1];
    const float* Ws    = (const float*)d_in[2];
    const float* bs    = (const float*)d_in[3];
    const float* qs    = (const float*)d_in[4];
    const float* qbs   = (const float*)d_in[5];
    const float* Wm    = (const float*)d_in[6];
    const float* bm    = (const float*)d_in[7];
    const float* qm    = (const float*)d_in[8];
    const float* qbm   = (const float*)d_in[9];
    const float* Wp    = (const float*)d_in[10];
    const float* bp    = (const float*)d_in[11];
    const float* gamma = (const float*)d_in[12];
    const float* beta  = (const float*)d_in[13];
    const float* rmean = (const float*)d_in[14];
    const float* rvar  = (const float*)d_in[15];
    const float* W1    = (const float*)d_in[16];
    const float* b1    = (const float*)d_in[17];
    const float* W2    = (const float*)d_in[18];
    const float* b2    = (const float*)d_in[19];
    float* out = (float*)d_out;

    k1_wh1<<<(BB * HH * NN) / 256, 256>>>(x, Ws, bs, qs, qbs);
    k3v<<<256, 256>>>(Wm, bm, qm, qbm);
    kC_conv<<<dim3(NN / 8, BB), 256>>>(adj);
    k2_mma<<<dim3(NN / 64, BB), 256>>>();             // 4th launch -> ncu target
    k4_wfrag<<<128, 256>>>();
    k5a_mma<<<dim3(8, 4, BB), 256>>>();
    k5b_partial<<<dim3(8, BB), 256>>>();
    k6_mlp<<<BB, 256>>>(Wm, bm, Wp, bp, gamma, beta, rmean, rvar, W1, b1, W2, b2, out);
}

// round 9
// speedup vs baseline: 2.9070x; 1.0369x over previous
#include <cuda_runtime.h>
#include <cuda_fp16.h>
#include <cstdint>
#include <cstddef>

// Shapes
#define BB   16
#define NN   1024
#define FIN  7
#define HH   8
#define DD   32
#define EMB  256
#define LOG2E 1.4426950408889634f
#define LN2  0.6931471805599453f

// ---------------- scratch ----------------
__device__ __half g_adjh[BB * NN * NN];       // half adj, 32 MB
__device__ uint4  g_Bf4 [BB * HH * 64 * 64];  // frag-packed Wh, 8 MB
__device__ float g_c1 [BB * HH * NN];
__device__ float g_h1 [BB * NN * EMB];        // [b][n][h*32+d] 16 MB
__device__ float g_c2 [BB * HH * NN];         // k2 accumulates h1.v
__device__ float g_g  [BB * HH * NN];
__device__ float g_v  [HH * EMB];
__device__ float g_cb [HH];
__device__ float g_u  [BB * HH * EMB];
__device__ float4 g_R4[BB * NN];              // row power sums R1..R4
__device__ float g_R5 [BB * NN];
__device__ float g_s0 [BB * HH];

// ---------------- half2 helpers ----------------
__device__ __forceinline__ uint32_t h2exp2_u(uint32_t x) {
    uint32_t r; asm("ex2.approx.f16x2 %0, %1;" : "=r"(r) : "r"(x)); return r;
}
__device__ __forceinline__ uint32_t h2mul_u(uint32_t a, uint32_t b) {
    uint32_t r; asm("mul.f16x2 %0, %1, %2;" : "=r"(r) : "r"(a), "r"(b)); return r;
}
__device__ __forceinline__ uint32_t f22h2_u(float hi, float lo) {
    uint32_t r; asm("cvt.rn.f16x2.f32 %0, %1, %2;" : "=r"(r) : "f"(hi), "f"(lo)); return r;
}
__device__ __forceinline__ uint32_t f2h2b(float a) {
    uint32_t r;
    asm("{ .reg .f16 v; cvt.rn.f16.f32 v, %1; mov.b32 %0, {v, v}; }" : "=r"(r) : "f"(a));
    return r;
}
__device__ __forceinline__ float2 h22f2(uint32_t h) {
    float2 f;
    asm("{ .reg .f16 l, hh; mov.b32 {l, hh}, %2; cvt.f32.f16 %0, l; cvt.f32.f16 %1, hh; }"
        : "=f"(f.x), "=f"(f.y) : "r"(h));
    return f;
}

#define CP_ASYNC16(dst, src) \
    asm volatile("cp.async.cg.shared.global [%0], [%1], 16;" :: "r"(dst), "l"(src) : "memory")
#define CP_COMMIT() asm volatile("cp.async.commit_group;" ::: "memory")
#define CP_WAIT(n)  asm volatile("cp.async.wait_group %0;" :: "n"(n) : "memory")

#define MMA_F16(c, a0, a1, a2, a3, b0, b1) \
    asm volatile("mma.sync.aligned.m16n8k16.row.col.f32.f16.f16.f32 " \
        "{%0,%1,%2,%3}, {%4,%5,%6,%7}, {%8,%9}, {%0,%1,%2,%3};" \
        : "+f"((c)[0]), "+f"((c)[1]), "+f"((c)[2]), "+f"((c)[3]) \
        : "r"(a0), "r"(a1), "r"(a2), "r"(a3), "r"(b0), "r"(b1))

#define LDSM_X4(r0, r1, r2, r3, a) \
    asm volatile("ldmatrix.sync.aligned.m8n8.x4.shared.b16 {%0,%1,%2,%3}, [%4];" \
        : "=r"(r0), "=r"(r1), "=r"(r2), "=r"(r3) : "r"(a))

#define LDSM_X4_T(r0, r1, r2, r3, a) \
    asm volatile("ldmatrix.sync.aligned.m8n8.x4.trans.shared.b16 {%0,%1,%2,%3}, [%4];" \
        : "=r"(r0), "=r"(r1), "=r"(r2), "=r"(r3) : "r"(a))

__device__ __forceinline__ uint32_t smem_u32(const void* p) {
    uint32_t a;
    asm("{ .reg .u64 t; cvta.to.shared.u64 t, %1; cvt.u32.u64 %0, t; }" : "=r"(a) : "l"(p));
    return a;
}

// ---------------- K1f: Wh -> frag-packed g_Bf4; c1; zero c2; (+ fused k3v) ----------------
// blocks [0,512): k1 work. blocks [512,768): v[h][k], cb[h].
__global__ __launch_bounds__(256) void k1_fused(
    const float* __restrict__ x,  const float* __restrict__ Ws,
    const float* __restrict__ bs, const float* __restrict__ qs,
    const float* __restrict__ qbs,
    const float* __restrict__ Wm, const float* __restrict__ bm,
    const float* __restrict__ qm, const float* __restrict__ qbm)
{
    int t = threadIdx.x;
    if (blockIdx.x >= 512) {
        int bx = blockIdx.x - 512;
        int wg = bx * 8 + (t >> 5);
        int lane = t & 31;
        int h = wg >> 8, k = wg & 255;
        float q = qm[h * 64 + lane] + qm[h * 64 + 32 + lane];
        float s = Wm[((size_t)(h * EMB + k)) * DD + lane] * q;
#pragma unroll
        for (int off = 16; off; off >>= 1) s += __shfl_xor_sync(0xffffffffu, s, off);
        if (lane == 0) g_v[h * EMB + k] = s;
        if (bx == 0) {
            int w = t >> 5;
            float q2 = qm[w * 64 + lane] + qm[w * 64 + 32 + lane];
            float s2 = bm[w * DD + lane] * q2;
#pragma unroll
            for (int off = 16; off; off >>= 1) s2 += __shfl_xor_sync(0xffffffffu, s2, off);
            if (lane == 0) g_cb[w] = s2 + qbm[w];
        }
        return;
    }

    __shared__ __half swh[32][264];
    int idx = blockIdx.x * 256 + t;
    int n = idx & (NN - 1);
    int h = (idx >> 10) & (HH - 1);
    int b = idx >> 13;

    g_c2[idx] = 0.f;

    float xv[FIN];
    const float* xr = x + ((size_t)(b * NN + n)) * FIN;
#pragma unroll
    for (int i = 0; i < FIN; i++) xv[i] = xr[i];

    const float* W = Ws + h * FIN * DD;
    float s = qbs[h];
#pragma unroll
    for (int d = 0; d < DD; d++) {
        float acc = bs[h * DD + d];
#pragma unroll
        for (int i = 0; i < FIN; i++) acc += xv[i] * W[i * DD + d];
        swh[d][t] = __float2half_rn(acc);
        s += acc * (qs[h * 2 * DD + d] + qs[h * 2 * DD + DD + d]);
    }
    g_c1[idx] = s > 0.f ? s : 0.01f * s;
    __syncthreads();

    int lane = t & 31, gid = lane >> 2, tig = lane & 3;
    int ksg_base = (blockIdx.x & 3) * 16;
#pragma unroll
    for (int q = 0; q < 2; q++) {
        int ksg_l = q * 8 + (t >> 5);
        int kb = ksg_l * 16 + 2 * tig;
        uint32_t u0[4], u1[4];
#pragma unroll
        for (int nt = 0; nt < 4; nt++) {
            u0[nt] = *(const uint32_t*)&swh[nt * 8 + gid][kb];
            u1[nt] = *(const uint32_t*)&swh[nt * 8 + gid][kb + 8];
        }
        uint4* dst = g_Bf4 + ((size_t)((b * HH + h) * 64 + ksg_base + ksg_l)) * 64;
        dst[lane]      = make_uint4(u0[0], u1[0], u0[1], u1[1]);
        dst[32 + lane] = make_uint4(u0[2], u1[2], u0[3], u1[3]);
    }
}

// ---------------- kC: adj -> half; R1..R5; zero g_g, g_s0, g_u ----------------
__global__ __launch_bounds__(256) void kC_conv(const float* __restrict__ adj)
{
    int b = blockIdx.y;
    int t = threadIdx.x;
    if (t < 64) g_g[b * (HH * NN) + blockIdx.x * 64 + t] = 0.f;
    if (blockIdx.x == 0 && b == 0 && t < BB * HH) g_s0[t] = 0.f;
    if (blockIdx.x < 8) g_u[b * (HH * EMB) + blockIdx.x * 256 + t] = 0.f;

    int w = t >> 5, lane = t & 31;
    int i = blockIdx.x * 8 + w;
    const float4* row = (const float4*)(adj + ((size_t)(b * NN + i)) * NN);
    __half* hrow = g_adjh + ((size_t)(b * NN + i)) * NN;

    float r1 = 0.f, r2 = 0.f, r3 = 0.f, r4 = 0.f, r5 = 0.f;
#pragma unroll
    for (int q = 0; q < 8; q++) {
        float4 va = row[q * 32 + lane];
        uint2 pk = make_uint2(f22h2_u(va.y, va.x), f22h2_u(va.w, va.z));
        *(uint2*)(hrow + 4 * (q * 32 + lane)) = pk;
        float vv[4] = {va.x, va.y, va.z, va.w};
#pragma unroll
        for (int e = 0; e < 4; e++) {
            float a = vv[e], a2 = a * a, a3 = a2 * a;
            r1 += a; r2 += a2; r3 += a3; r4 += a2 * a2; r5 += a2 * a3;
        }
    }
#pragma unroll
    for (int off = 16; off; off >>= 1) {
        r1 += __shfl_xor_sync(0xffffffffu, r1, off);
        r2 += __shfl_xor_sync(0xffffffffu, r2, off);
        r3 += __shfl_xor_sync(0xffffffffu, r3, off);
        r4 += __shfl_xor_sync(0xffffffffu, r4, off);
        r5 += __shfl_xor_sync(0xffffffffu, r5, off);
    }
    if (lane == 0) {
        g_R4[b * NN + i] = make_float4(r1, r2, r3, r4);
        g_R5[b * NN + i] = r5;
    }
}

// ---------------- K2: attention; K-tile 128; Taylor Z (no z-MMA) ----------------
__global__ __launch_bounds__(256, 2) void k2_mma()
{
    __shared__ __align__(16) uint32_t adj_hs[2][64 * 68];   // 34.8 KB
    __shared__ float v_s[HH * EMB];                          // 8 KB

    int t = threadIdx.x;
    int lane = t & 31, h = t >> 5;
    int gid = lane >> 2, tig = lane & 3;
    int i0 = blockIdx.x * 64, b = blockIdx.y;

#pragma unroll
    for (int p = 0; p < 8; p++) v_s[p * 256 + t] = g_v[p * 256 + t];

    const __half* adjhb = g_adjh + (size_t)b * NN * NN;
    const uint4* Bf = g_Bf4 + (size_t)(b * HH + h) * 64 * 64;
    const float* c1p  = g_c1 + (b * HH + h) * NN + i0;

    uint32_t clb[4][2];
#pragma unroll
    for (int mt = 0; mt < 4; mt++) {
        clb[mt][0] = f2h2b(c1p[mt * 16 + gid]     * LOG2E);
        clb[mt][1] = f2h2b(c1p[mt * 16 + gid + 8] * LOG2E);
    }

    float acc[4][4][4];
#pragma unroll
    for (int mt = 0; mt < 4; mt++)
#pragma unroll
        for (int nt = 0; nt < 4; nt++)
#pragma unroll
            for (int r = 0; r < 4; r++) acc[mt][nt][r] = 0.f;

    uint32_t sbase = smem_u32(adj_hs);
    uint32_t lane_off = (((lane & 7) + ((lane >> 3) & 1) * 8) * 272) + ((lane >> 4) & 1) * 16;

#define PREFETCH(tile, buf) do { \
        uint32_t dst0 = sbase + (buf) * 17408u; \
        const __half* srcb = adjhb + (size_t)i0 * NN + (tile) * 128; \
        _Pragma("unroll") \
        for (int p = 0; p < 4; p++) { \
            int idx = p * 256 + t; \
            int row = idx >> 4, c = idx & 15; \
            CP_ASYNC16(dst0 + row * 272 + c * 16, \
                       srcb + (size_t)row * NN + c * 8); \
        } \
        CP_COMMIT(); \
    } while (0)

    PREFETCH(0, 0);

#pragma unroll 1
    for (int tile = 0; tile < 8; tile++) {
        if (tile + 1 < 8) { PREFETCH(tile + 1, (tile + 1) & 1); CP_WAIT(1); }
        else              { CP_WAIT(0); }
        __syncthreads();
        uint32_t tb = sbase + (tile & 1) * 17408u + lane_off;

#pragma unroll
        for (int ks = 0; ks < 8; ks++) {
            uint4 rB0 = Bf[(tile * 8 + ks) * 64 + lane];
            uint4 rB1 = Bf[(tile * 8 + ks) * 64 + 32 + lane];
#pragma unroll
            for (int mt = 0; mt < 4; mt++) {
                uint32_t r0, r1, r2, r3;
                LDSM_X4(r0, r1, r2, r3, tb + mt * 4352 + ks * 32);
                uint32_t a0 = h2exp2_u(h2mul_u(clb[mt][0], r0));
                uint32_t a1 = h2exp2_u(h2mul_u(clb[mt][1], r1));
                uint32_t a2 = h2exp2_u(h2mul_u(clb[mt][0], r2));
                uint32_t a3 = h2exp2_u(h2mul_u(clb[mt][1], r3));
                MMA_F16(acc[mt][0], a0, a1, a2, a3, rB0.x, rB0.y);
                MMA_F16(acc[mt][1], a0, a1, a2, a3, rB0.z, rB0.w);
                MMA_F16(acc[mt][2], a0, a1, a2, a3, rB1.x, rB1.y);
                MMA_F16(acc[mt][3], a0, a1, a2, a3, rB1.z, rB1.w);
            }
        }
        __syncthreads();
    }
#undef PREFETCH

#pragma unroll
    for (int mt = 0; mt < 4; mt++) {
        int r0 = i0 + mt * 16 + gid;
        // Taylor Z with the SAME half-rounded c the E values used
        float lc0 = h22f2(clb[mt][0]).x * LN2;
        float lc1 = h22f2(clb[mt][1]).x * LN2;
        float4 Ra = g_R4[b * NN + r0];     float R5a = g_R5[b * NN + r0];
        float4 Rb = g_R4[b * NN + r0 + 8]; float R5b = g_R5[b * NN + r0 + 8];
        float Z0 = 1024.f + lc0 * (Ra.x + lc0 * (0.5f * Ra.y + lc0 * ((1.f / 6.f) * Ra.z
                     + lc0 * ((1.f / 24.f) * Ra.w + lc0 * ((1.f / 120.f) * R5a)))));
        float Z1 = 1024.f + lc1 * (Rb.x + lc1 * (0.5f * Rb.y + lc1 * ((1.f / 6.f) * Rb.z
                     + lc1 * ((1.f / 24.f) * Rb.w + lc1 * ((1.f / 120.f) * R5b)))));
        float zi0 = 1.f / Z0, zi1 = 1.f / Z1;

        float* o0 = g_h1 + ((size_t)(b * NN + r0)) * EMB + h * 32;
        float* o1 = o0 + (size_t)8 * EMB;
        float q0[4][2], q1[4][2];
#pragma unroll
        for (int nt = 0; nt < 4; nt++) {
            q0[nt][0] = acc[mt][nt][0] * zi0; q0[nt][1] = acc[mt][nt][1] * zi0;
            q1[nt][0] = acc[mt][nt][2] * zi1; q1[nt][1] = acc[mt][nt][3] * zi1;
            *(float2*)(o0 + nt * 8 + 2 * tig) = make_float2(q0[nt][0], q0[nt][1]);
            *(float2*)(o1 + nt * 8 + 2 * tig) = make_float2(q1[nt][0], q1[nt][1]);
        }
#pragma unroll
        for (int th = 0; th < HH; th++) {
            float p0 = 0.f, p1 = 0.f;
#pragma unroll
            for (int nt = 0; nt < 4; nt++) {
                float2 vv = *(const float2*)&v_s[th * 256 + h * 32 + nt * 8 + 2 * tig];
                p0 += q0[nt][0] * vv.x + q0[nt][1] * vv.y;
                p1 += q1[nt][0] * vv.x + q1[nt][1] * vv.y;
            }
            p0 += __shfl_xor_sync(0xffffffffu, p0, 1);
            p0 += __shfl_xor_sync(0xffffffffu, p0, 2);
            p1 += __shfl_xor_sync(0xffffffffu, p1, 1);
            p1 += __shfl_xor_sync(0xffffffffu, p1, 2);
            if (tig == 0) {
                atomicAdd(&g_c2[(b * HH + th) * NN + r0], p0);
                atomicAdd(&g_c2[(b * HH + th) * NN + r0 + 8], p1);
            }
        }
    }
}

// ---------------- K5a: (absorbs k4w) weights in smem; column sums via MMA ----------------
// grid (8 jblk, 4 isplit, 16 b), 256 thr, warp owns 16 j.
__global__ __launch_bounds__(256) void k5a_mma()
{
    __shared__ __align__(16) uint32_t at[2][16 * 68];   // 8.7 KB
    __shared__ __half wsm[32][264];                      // 16.5 KB, stride 528B

    int t = threadIdx.x, lane = t & 31, w = t >> 5;
    int jb = blockIdx.x, iq = blockIdx.y, b = blockIdx.z;
    int j0 = jb * 128, i0c = iq * 256;
    int jw = w * 16;

    // prologue: Taylor weights for this CTA's 256 i's, all heads
    {
        int i = i0c + t;
        float4 R = g_R4[b * NN + i];
        float R5v = g_R5[b * NN + i];
#pragma unroll
        for (int h = 0; h < HH; h++) {
            float raw = g_c2[(b * HH + h) * NN + i] + g_cb[h];
            float c = raw > 0.f ? raw : 0.01f * raw;
            float Z = 1024.f + c * (R.x + c * (0.5f * R.y + c * ((1.f / 6.f) * R.z
                        + c * ((1.f / 24.f) * R.w + c * ((1.f / 120.f) * R5v)))));
            float z = 1024.f / Z;
            float w1 = z * c;
            float w2 = w1 * c * 0.5f;
            float w3 = w2 * c * (1.f / 3.f);
            float w4 = w3 * c * 0.25f;
            wsm[0 * 8 + h][t] = __float2half_rn(w1);
            wsm[1 * 8 + h][t] = __float2half_rn(w2);
            wsm[2 * 8 + h][t] = __float2half_rn(w3);
            wsm[3 * 8 + h][t] = __float2half_rn(w4);
            if (jb == 0) {
                float s = z;
#pragma unroll
                for (int off = 16; off; off >>= 1)
                    s += __shfl_xor_sync(0xffffffffu, s, off);
                if (lane == 0) atomicAdd(&g_s0[b * HH + h], s);
            }
        }
    }
    __syncthreads();

    const __half* adjb = g_adjh + (size_t)b * NN * NN;
    uint32_t sbase = smem_u32(at);

    int grp = lane >> 3, r = lane & 7;
    int row = (grp >= 2) ? 8 + r : r;
    int colh = ((grp & 1) ? jw + 8 : jw);
    uint32_t loff = (uint32_t)(row * 272 + colh * 2);

    int hB = lane >> 2, tigB = lane & 3;

    float acc[4] = {0.f, 0.f, 0.f, 0.f};

#define PRE5(step, buf) do { \
        uint32_t dst0 = sbase + (buf) * (16 * 68 * 4); \
        const __half* srcb = adjb + (size_t)(i0c + (step) * 16) * NN + j0; \
        int rw = t >> 4, c = t & 15; \
        CP_ASYNC16(dst0 + rw * 272 + c * 16, srcb + (size_t)rw * NN + c * 8); \
        CP_COMMIT(); \
    } while (0)

    PRE5(0, 0);

#pragma unroll 1
    for (int step = 0; step < 16; step++) {
        if (step + 1 < 16) { PRE5(step + 1, (step + 1) & 1); CP_WAIT(1); }
        else               { CP_WAIT(0); }
        __syncthreads();

        int ibh = step * 16 + 2 * tigB;
        uint32_t bm0[4], bm1[4];
#pragma unroll
        for (int m = 0; m < 4; m++) {
            bm0[m] = *(const uint32_t*)&wsm[m * 8 + hB][ibh];
            bm1[m] = *(const uint32_t*)&wsm[m * 8 + hB][ibh + 8];
        }

        uint32_t a1[4];
        LDSM_X4_T(a1[0], a1[1], a1[2], a1[3],
                  sbase + (step & 1) * (16 * 68 * 4) + loff);
        uint32_t a2[4], a3[4], a4[4];
#pragma unroll
        for (int q = 0; q < 4; q++) {
            a2[q] = h2mul_u(a1[q], a1[q]);
            a3[q] = h2mul_u(a2[q], a1[q]);
            a4[q] = h2mul_u(a2[q], a2[q]);
        }
        MMA_F16(acc, a1[0], a1[1], a1[2], a1[3], bm0[0], bm1[0]);
        MMA_F16(acc, a2[0], a2[1], a2[2], a2[3], bm0[1], bm1[1]);
        MMA_F16(acc, a3[0], a3[1], a3[2], a3[3], bm0[2], bm1[2]);
        MMA_F16(acc, a4[0], a4[1], a4[2], a4[3], bm0[3], bm1[3]);
        __syncthreads();
    }
#undef PRE5

    int jg1 = j0 + jw + (lane >> 2);
    int jg2 = jg1 + 8;
    int hc = 2 * (lane & 3);
    atomicAdd(&g_g[(b * HH + hc)     * NN + jg1], acc[0]);
    atomicAdd(&g_g[(b * HH + hc + 1) * NN + jg1], acc[1]);
    atomicAdd(&g_g[(b * HH + hc)     * NN + jg2], acc[2]);
    atomicAdd(&g_g[(b * HH + hc + 1) * NN + jg2], acc[3]);
}

// ---------------- K5b: partial u = sum_{j in block} gtilde_j * h1_j ----------------
__global__ __launch_bounds__(256) void k5b_partial()
{
    __shared__ float gt[HH][128];
    int b = blockIdx.y, jb = blockIdx.x * 128;
    int t = threadIdx.x;

#pragma unroll
    for (int p = 0; p < 4; p++) {
        int idx = p * 256 + t;
        int h = idx >> 7, j = idx & 127;
        gt[h][j] = (g_g[(b * HH + h) * NN + jb + j] + g_s0[b * HH + h]) * (1.f / 1024.f);
    }
    __syncthreads();

    float u[HH];
#pragma unroll
    for (int h = 0; h < HH; h++) u[h] = 0.f;

    const float* h1p = g_h1 + ((size_t)(b * NN + jb)) * EMB + t;
#pragma unroll 4
    for (int j = 0; j < 128; j++) {
        float hv = h1p[(size_t)j * EMB];
#pragma unroll
        for (int h = 0; h < HH; h++) u[h] += gt[h][j] * hv;
    }
#pragma unroll
    for (int h = 0; h < HH; h++)
        atomicAdd(&g_u[(b * HH + h) * EMB + t], u[h]);
}

// ---------------- K6: p = u@Wm + 1024*bm, then MLP head ----------------
__global__ __launch_bounds__(256) void k6_mlp(
    const float* __restrict__ Wm, const float* __restrict__ bm,
    const float* __restrict__ Wp, const float* __restrict__ bp,
    const float* __restrict__ gamma, const float* __restrict__ beta,
    const float* __restrict__ rmean, const float* __restrict__ rvar,
    const float* __restrict__ W1, const float* __restrict__ b1,
    const float* __restrict__ W2, const float* __restrict__ b2,
    float* __restrict__ out)
{
    __shared__ float u_sm[HH * EMB];
    __shared__ float p_s[256];
    __shared__ float y_s[512];
    __shared__ float z_s[256];
    __shared__ float w_s[128];
    int b = blockIdx.x, t = threadIdx.x;

#pragma unroll
    for (int p = 0; p < 8; p++) u_sm[p * 256 + t] = g_u[b * (HH * EMB) + p * 256 + t];
    __syncthreads();

    {
        int h = t >> 5, d = t & 31;
        float acc = 1024.f * bm[h * DD + d];
        const float* wm = Wm + (size_t)h * EMB * DD + d;
#pragma unroll 4
        for (int k = 0; k < EMB; k++) acc += u_sm[h * EMB + k] * wm[(size_t)k * DD];
        p_s[t] = acc;
    }
    __syncthreads();

#pragma unroll
    for (int r = 0; r < 2; r++) {
        int o = r * 256 + t;
        float acc = bp[o];
#pragma unroll 4
        for (int k = 0; k < 256; k++) acc += p_s[k] * Wp[k * 512 + o];
        acc = (acc - rmean[o]) * rsqrtf(rvar[o] + 1e-5f) * gamma[o] + beta[o];
        y_s[o] = fmaxf(acc, 0.f);
    }
    __syncthreads();
    {
        float acc = b1[t];
#pragma unroll 4
        for (int k = 0; k < 512; k++) acc += y_s[k] * W1[k * 256 + t];
        z_s[t] = fmaxf(acc, 0.f);
    }
    __syncthreads();
    if (t < 128) {
        float acc = b2[t];
#pragma unroll 4
        for (int k = 0; k < 256; k++) acc += z_s[k] * W2[k * 128 + t];
        w_s[t] = fmaxf(acc, 0.f);
    }
    __syncthreads();
    if (t < 64) w_s[t] += w_s[t + 64];
    __syncthreads();
    if (t < 32) {
        float v = w_s[t] + w_s[t + 32];
#pragma unroll
        for (int off = 16; off; off >>= 1) v += __shfl_xor_sync(0xffffffffu, v, off);
        if (t == 0) out[b] = v * (1.f / 128.f);
    }
}

// ---------------- launch ----------------
extern "C" void kernel_launch(void* const* d_in, const int* in_sizes, int n_in,
                              void* d_out, int out_size)
{
    const float* x     = (const float*)d_in[0];
    const float* adj   = (const float*)d_in[1];
    const float* Ws    = (const float*)d_in[2];
    const float* bs    = (const float*)d_in[3];
    const float* qs    = (const float*)d_in[4];
    const float* qbs   = (const float*)d_in[5];
    const float* Wm    = (const float*)d_in[6];
    const float* bm    = (const float*)d_in[7];
    const float* qm    = (const float*)d_in[8];
    const float* qbm   = (const float*)d_in[9];
    const float* Wp    = (const float*)d_in[10];
    const float* bp    = (const float*)d_in[11];
    const float* gamma = (const float*)d_in[12];
    const float* beta  = (const float*)d_in[13];
    const float* rmean = (const float*)d_in[14];
    const float* rvar  = (const float*)d_in[15];
    const float* W1    = (const float*)d_in[16];
    const float* b1    = (const float*)d_in[17];
    const float* W2    = (const float*)d_in[18];
    const float* b2    = (const float*)d_in[19];
    float* out = (float*)d_out;

    k1_fused<<<768, 256>>>(x, Ws, bs, qs, qbs, Wm, bm, qm, qbm);
    kC_conv<<<dim3(NN / 8, BB), 256>>>(adj);
    k2_mma<<<dim3(NN / 64, BB), 256>>>();
    k5a_mma<<<dim3(8, 4, BB), 256>>>();               // 4th launch -> ncu target
    k5b_partial<<<dim3(8, BB), 256>>>();
    k6_mlp<<<BB, 256>>>(Wm, bm, Wp, bp, gamma, beta, rmean, rvar, W1, b1, W2, b2, out);
}